// round 7
// baseline (speedup 1.0000x reference)
#include <cuda_runtime.h>
#include <cuda_bf16.h>
#include <cstdint>

#define TDIM 2048
#define DDIM 64
#define BH 32
#define BQ 128
#define BK 64
#define NTH 512
#define KTILES (TDIM / BK)

// smem layout (bytes)
#define QH_OFF 0
#define QL_OFF 16384
#define PH_OFF 32768
#define PL_OFF 49152
#define KV_OFF 65536
#define KV_STAGE 32768
#define SMEM_BYTES (KV_OFF + 2 * KV_STAGE)   // 128 KB

#define NELEM ((size_t)BH * TDIM * DDIM)

__device__ unsigned int g_maskbits[(size_t)TDIM * TDIM / 32];  // 512 KB
__device__ uint4 g_qh[NELEM / 8], g_ql[NELEM / 8];
__device__ uint4 g_kh[NELEM / 8], g_kl[NELEM / 8];
__device__ uint4 g_vh[NELEM / 8], g_vl[NELEM / 8];

// ---------------- helpers ----------------
__device__ __forceinline__ uint32_t smem_u32(const void* p) {
    uint32_t a;
    asm("{ .reg .u64 t; cvta.to.shared.u64 t, %1; cvt.u32.u64 %0, t; }" : "=r"(a) : "l"(p));
    return a;
}
__device__ __forceinline__ uint32_t swz(uint32_t byte) {
    return byte ^ ((byte >> 3) & 0x70);
}
__device__ __forceinline__ void cp16(uint32_t dst, const void* src) {
    asm volatile("cp.async.cg.shared.global [%0], [%1], 16;" :: "r"(dst), "l"(src));
}
#define CP_COMMIT() asm volatile("cp.async.commit_group;" ::: "memory")
#define CP_WAIT(n)  asm volatile("cp.async.wait_group %0;" :: "n"(n) : "memory")

__device__ __forceinline__ void ldsm_x4(uint32_t (&r)[4], uint32_t addr) {
    asm volatile("ldmatrix.sync.aligned.m8n8.x4.shared.b16 {%0,%1,%2,%3}, [%4];"
                 : "=r"(r[0]), "=r"(r[1]), "=r"(r[2]), "=r"(r[3]) : "r"(addr));
}
__device__ __forceinline__ void ldsm_x4_t(uint32_t (&r)[4], uint32_t addr) {
    asm volatile("ldmatrix.sync.aligned.m8n8.x4.trans.shared.b16 {%0,%1,%2,%3}, [%4];"
                 : "=r"(r[0]), "=r"(r[1]), "=r"(r[2]), "=r"(r[3]) : "r"(addr));
}
__device__ __forceinline__ void mma16816(float (&c)[4], const uint32_t (&a)[4],
                                         uint32_t b0, uint32_t b1) {
    asm volatile(
        "mma.sync.aligned.m16n8k16.row.col.f32.bf16.bf16.f32 "
        "{%0,%1,%2,%3}, {%4,%5,%6,%7}, {%8,%9}, {%0,%1,%2,%3};"
        : "+f"(c[0]), "+f"(c[1]), "+f"(c[2]), "+f"(c[3])
        : "r"(a[0]), "r"(a[1]), "r"(a[2]), "r"(a[3]), "r"(b0), "r"(b1));
}
__device__ __forceinline__ float ex2f(float x) {
    float r;
    asm("ex2.approx.f32 %0, %1;" : "=f"(r) : "f"(x));
    return r;
}
__device__ __forceinline__ uint32_t pack_bf16x2(float x, float y) {
    __nv_bfloat16 hx = __float2bfloat16(x), hy = __float2bfloat16(y);
    return ((uint32_t)__bfloat16_as_ushort(hy) << 16) | __bfloat16_as_ushort(hx);
}
__device__ __forceinline__ void cvt_pair_store(char* smem, uint32_t hi_off, uint32_t lo_off,
                                               uint32_t byte, float x, float y) {
    __nv_bfloat16 hx = __float2bfloat16(x), hy = __float2bfloat16(y);
    float rx = x - __bfloat162float(hx), ry = y - __bfloat162float(hy);
    uint32_t sw = swz(byte);
    *(uint32_t*)(smem + hi_off + sw) =
        ((uint32_t)__bfloat16_as_ushort(hy) << 16) | __bfloat16_as_ushort(hx);
    *(uint32_t*)(smem + lo_off + sw) = pack_bf16x2(rx, ry);
}

// ---------------- prepass kernels ----------------
__global__ void pack_mask(const int* __restrict__ m) {
    int w = blockIdx.x * blockDim.x + threadIdx.x;
    if (w >= (TDIM * TDIM) / 32) return;
    const int4* p = (const int4*)(m + (size_t)w * 32);
    unsigned int bits = 0;
    #pragma unroll
    for (int i = 0; i < 8; ++i) {
        int4 v = p[i];
        bits |= (unsigned)(v.x != 0) << (i * 4);
        bits |= (unsigned)(v.y != 0) << (i * 4 + 1);
        bits |= (unsigned)(v.z != 0) << (i * 4 + 2);
        bits |= (unsigned)(v.w != 0) << (i * 4 + 3);
    }
    g_maskbits[w] = bits;
}

__global__ void cvt_split(const float4* __restrict__ src, uint4* __restrict__ hi,
                          uint4* __restrict__ lo, float scale, int n16) {
    int i = blockIdx.x * blockDim.x + threadIdx.x;
    if (i >= n16) return;
    float4 a = src[2 * i], b = src[2 * i + 1];
    a.x *= scale; a.y *= scale; a.z *= scale; a.w *= scale;
    b.x *= scale; b.y *= scale; b.z *= scale; b.w *= scale;
    __nv_bfloat16 h[8] = {
        __float2bfloat16(a.x), __float2bfloat16(a.y), __float2bfloat16(a.z), __float2bfloat16(a.w),
        __float2bfloat16(b.x), __float2bfloat16(b.y), __float2bfloat16(b.z), __float2bfloat16(b.w)};
    uint4 hw, lw;
    hw.x = ((uint32_t)__bfloat16_as_ushort(h[1]) << 16) | __bfloat16_as_ushort(h[0]);
    hw.y = ((uint32_t)__bfloat16_as_ushort(h[3]) << 16) | __bfloat16_as_ushort(h[2]);
    hw.z = ((uint32_t)__bfloat16_as_ushort(h[5]) << 16) | __bfloat16_as_ushort(h[4]);
    hw.w = ((uint32_t)__bfloat16_as_ushort(h[7]) << 16) | __bfloat16_as_ushort(h[6]);
    lw.x = pack_bf16x2(a.x - __bfloat162float(h[0]), a.y - __bfloat162float(h[1]));
    lw.y = pack_bf16x2(a.z - __bfloat162float(h[2]), a.w - __bfloat162float(h[3]));
    lw.z = pack_bf16x2(b.x - __bfloat162float(h[4]), b.y - __bfloat162float(h[5]));
    lw.w = pack_bf16x2(b.z - __bfloat162float(h[6]), b.w - __bfloat162float(h[7]));
    hi[i] = hw;
    lo[i] = lw;
}

// ---------------- main kernel: 16 warps, N/K-split warp pairs ----------------
__global__ __launch_bounds__(NTH, 1)
void fa_mma(float* __restrict__ go)
{
    extern __shared__ char smem[];
    const uint32_t sb = smem_u32(smem);
    const int tid = threadIdx.x;
    const int lane = tid & 31, wid = tid >> 5;
    const int ch = wid & 1;           // column-half / k-half selector
    const int pr = wid >> 1;          // warp-pair id -> 16-row Q band
    const int m0 = pr * 16;
    const int bh = blockIdx.y;
    const int q0 = blockIdx.x * BQ;

    const size_t row_bytes = 128;
    const char* gqh = (const char*)g_qh + ((size_t)bh * TDIM + q0) * row_bytes;
    const char* gql = (const char*)g_ql + ((size_t)bh * TDIM + q0) * row_bytes;
    const char* gkh0 = (const char*)g_kh + (size_t)bh * TDIM * row_bytes;
    const char* gkl0 = (const char*)g_kl + (size_t)bh * TDIM * row_bytes;
    const char* gvh0 = (const char*)g_vh + (size_t)bh * TDIM * row_bytes;
    const char* gvl0 = (const char*)g_vl + (size_t)bh * TDIM * row_bytes;
    float* ob = go + (size_t)bh * TDIM * DDIM;

    // ---- prologue: async-load Q tile ----
    #pragma unroll
    for (int j = 0; j < 2; ++j) {
        uint32_t byte = (tid + j * NTH) * 16;
        uint32_t sw = swz(byte);
        cp16(sb + QH_OFF + sw, gqh + byte);
        cp16(sb + QL_OFF + sw, gql + byte);
    }
    CP_COMMIT();

    // ---- K/V tile 0 into stage 0 (each section 8KB = 512 chunks) ----
    {
        uint32_t byte = tid * 16;
        uint32_t sw = swz(byte);
        uint32_t base = sb + KV_OFF;
        cp16(base + sw,         gkh0 + byte);
        cp16(base + 8192 + sw,  gkl0 + byte);
        cp16(base + 16384 + sw, gvh0 + byte);
        cp16(base + 24576 + sw, gvl0 + byte);
    }
    CP_COMMIT();
    CP_WAIT(1);
    __syncthreads();

    // fragment address pieces
    const uint32_t arow  = m0 + ((lane >> 3) & 1) * 8 + (lane & 7);
    const uint32_t acol0 = (lane >> 4) * 16;
    const uint32_t brow  = ((lane >> 4) & 1) * 8 + (lane & 7);
    const uint32_t bcol0 = ((lane >> 3) & 1) * 16;
    const uint32_t trow0 = ((lane >> 3) & 1) * 8 + (lane & 7);
    const uint32_t tcol0 = ((lane >> 4) & 1) * 16;

    float oreg[8][4];
    #pragma unroll
    for (int i = 0; i < 8; ++i)
        #pragma unroll
        for (int j = 0; j < 4; ++j) oreg[i][j] = 0.f;
    float lsum0 = 0.f, lsum1 = 0.f;

    const int g  = lane >> 2;
    const int tq = lane & 3;
    const int r0loc = m0 + g;

    for (int kt = 0; kt < KTILES; ++kt) {
        if (kt + 1 < KTILES) {
            const size_t toff = (size_t)(kt + 1) * BK * row_bytes;
            uint32_t base = sb + KV_OFF + ((kt + 1) & 1) * KV_STAGE;
            uint32_t byte = tid * 16;
            uint32_t sw = swz(byte);
            cp16(base + sw,         gkh0 + toff + byte);
            cp16(base + 8192 + sw,  gkl0 + toff + byte);
            cp16(base + 16384 + sw, gvh0 + toff + byte);
            cp16(base + 24576 + sw, gvl0 + toff + byte);
            CP_COMMIT();
            CP_WAIT(1);
        } else {
            CP_WAIT(0);
        }

        // warp's 32-col mask words (early independent LDG)
        uint32_t mw0 = g_maskbits[(size_t)(q0 + r0loc) * (TDIM / 32) + kt * 2 + ch];
        uint32_t mw1 = g_maskbits[(size_t)(q0 + r0loc + 8) * (TDIM / 32) + kt * 2 + ch];
        __syncthreads();

        const uint32_t kvb = sb + KV_OFF + (kt & 1) * KV_STAGE;
        const uint32_t khb = kvb, klb = kvb + 8192, vhb = kvb + 16384, vlb = kvb + 24576;

        // ---- S = Q K^T over this warp's 32 n-cols (3-term bf16 emulation) ----
        float s[4][4];
        #pragma unroll
        for (int i = 0; i < 4; ++i)
            #pragma unroll
            for (int j = 0; j < 4; ++j) s[i][j] = 0.f;

        #pragma unroll
        for (int ks = 0; ks < 4; ++ks) {
            uint32_t swq = swz(arow * 128 + ks * 32 + acol0);
            uint32_t aQh[4], aQl[4];
            ldsm_x4(aQh, sb + QH_OFF + swq);
            ldsm_x4(aQl, sb + QL_OFF + swq);
            uint32_t bHf[2][4], bLf[2][4];
            #pragma unroll
            for (int np = 0; np < 2; ++np) {
                uint32_t nglob = ch * 2 + np;
                uint32_t sw = swz((nglob * 16 + brow) * 128 + ks * 32 + bcol0);
                ldsm_x4(bHf[np], khb + sw);
                ldsm_x4(bLf[np], klb + sw);
            }
            #pragma unroll
            for (int np = 0; np < 2; ++np) {
                mma16816(s[2 * np],     aQh, bHf[np][0], bHf[np][1]);
                mma16816(s[2 * np + 1], aQh, bHf[np][2], bHf[np][3]);
            }
            #pragma unroll
            for (int np = 0; np < 2; ++np) {
                mma16816(s[2 * np],     aQh, bLf[np][0], bLf[np][1]);
                mma16816(s[2 * np + 1], aQh, bLf[np][2], bLf[np][3]);
            }
            #pragma unroll
            for (int np = 0; np < 2; ++np) {
                mma16816(s[2 * np],     aQl, bHf[np][0], bHf[np][1]);
                mma16816(s[2 * np + 1], aQl, bHf[np][2], bHf[np][3]);
            }
        }

        // ---- mask + exp2 + write P (S already in log2 domain) ----
        #pragma unroll
        for (int j = 0; j < 4; ++j) {
            int c = (j >> 1) * 16 + (j & 1) * 8 + tq * 2;     // within warp's 32 cols
            float p0 = ((mw0 >> c) & 1u)       ? 0.f : ex2f(s[j][0]);
            float p1 = ((mw0 >> (c + 1)) & 1u) ? 0.f : ex2f(s[j][1]);
            float p2 = ((mw1 >> c) & 1u)       ? 0.f : ex2f(s[j][2]);
            float p3 = ((mw1 >> (c + 1)) & 1u) ? 0.f : ex2f(s[j][3]);
            lsum0 += p0 + p1;
            lsum1 += p2 + p3;
            uint32_t colg = ch * 32 + c;
            cvt_pair_store(smem, PH_OFF, PL_OFF, (uint32_t)(r0loc * 128 + colg * 2), p0, p1);
            cvt_pair_store(smem, PH_OFF, PL_OFF, (uint32_t)((r0loc + 8) * 128 + colg * 2), p2, p3);
        }
        __syncwarp();   // own-warp P visible across lanes for ldmatrix

        // ---- O += P V over this warp's 32-k slice (3-term) ----
        #pragma unroll
        for (int ks2 = 0; ks2 < 2; ++ks2) {
            uint32_t kbase = ch * 32 + ks2 * 16;
            uint32_t swA = swz(arow * 128 + kbase * 2 + acol0);
            uint32_t aPh[4], aPl[4];
            ldsm_x4(aPh, sb + PH_OFF + swA);
            ldsm_x4(aPl, sb + PL_OFF + swA);
            uint32_t bHf[4][4], bLf[4][4];
            #pragma unroll
            for (int np = 0; np < 4; ++np) {
                uint32_t swB = swz((kbase + trow0) * 128 + np * 32 + tcol0);
                ldsm_x4_t(bHf[np], vhb + swB);
                ldsm_x4_t(bLf[np], vlb + swB);
            }
            #pragma unroll
            for (int np = 0; np < 4; ++np) {
                mma16816(oreg[2 * np],     aPh, bHf[np][0], bHf[np][1]);
                mma16816(oreg[2 * np + 1], aPh, bHf[np][2], bHf[np][3]);
            }
            #pragma unroll
            for (int np = 0; np < 4; ++np) {
                mma16816(oreg[2 * np],     aPh, bLf[np][0], bLf[np][1]);
                mma16816(oreg[2 * np + 1], aPh, bLf[np][2], bLf[np][3]);
            }
            #pragma unroll
            for (int np = 0; np < 4; ++np) {
                mma16816(oreg[2 * np],     aPl, bHf[np][0], bHf[np][1]);
                mma16816(oreg[2 * np + 1], aPl, bHf[np][2], bHf[np][3]);
            }
        }
        __syncthreads();   // KV stage + P safe to reuse
    }

    // ---- epilogue: pair-wise reduce partial O and lsum ----
    #pragma unroll
    for (int off = 1; off <= 2; off <<= 1) {
        lsum0 += __shfl_xor_sync(0xffffffffu, lsum0, off);
        lsum1 += __shfl_xor_sync(0xffffffffu, lsum1, off);
    }
    __syncthreads();       // all PV reads of P done before red overwrite

    float* red  = (float*)(smem + PH_OFF);   // 32 KB: 8 pairs x 32 lanes x 8 frags x 4
    float* lred = (float*)(smem + QH_OFF);   // 256 floats
    if (ch == 1) {
        #pragma unroll
        for (int ng = 0; ng < 8; ++ng) {
            float* p = red + (((size_t)pr * 32 + lane) * 8 + ng) * 4;
            p[0] = oreg[ng][0]; p[1] = oreg[ng][1]; p[2] = oreg[ng][2]; p[3] = oreg[ng][3];
        }
        lred[r0loc] = lsum0;
        lred[r0loc + 8] = lsum1;
    }
    __syncthreads();

    if (ch == 0) {
        float inv0 = 1.f / (lsum0 + lred[r0loc]);
        float inv1 = 1.f / (lsum1 + lred[r0loc + 8]);
        float* orow0 = ob + (size_t)(q0 + r0loc) * DDIM;
        float* orow1 = ob + (size_t)(q0 + r0loc + 8) * DDIM;
        #pragma unroll
        for (int ng = 0; ng < 8; ++ng) {
            const float* p = red + (((size_t)pr * 32 + lane) * 8 + ng) * 4;
            int c = ng * 8 + tq * 2;
            *(float2*)(orow0 + c) = make_float2((oreg[ng][0] + p[0]) * inv0,
                                                (oreg[ng][1] + p[1]) * inv0);
            *(float2*)(orow1 + c) = make_float2((oreg[ng][2] + p[2]) * inv1,
                                                (oreg[ng][3] + p[3]) * inv1);
        }
    }
}

extern "C" void kernel_launch(void* const* d_in, const int* in_sizes, int n_in,
                              void* d_out, int out_size) {
    const float* q = (const float*)d_in[0];
    const float* k = (const float*)d_in[1];
    const float* v = (const float*)d_in[2];
    const int* mask = (const int*)d_in[3];
    float* out = (float*)d_out;

    uint4 *qh, *ql, *kh, *kl, *vh, *vl;
    cudaGetSymbolAddress((void**)&qh, g_qh);
    cudaGetSymbolAddress((void**)&ql, g_ql);
    cudaGetSymbolAddress((void**)&kh, g_kh);
    cudaGetSymbolAddress((void**)&kl, g_kl);
    cudaGetSymbolAddress((void**)&vh, g_vh);
    cudaGetSymbolAddress((void**)&vl, g_vl);

    pack_mask<<<(TDIM * TDIM / 32 + 255) / 256, 256>>>(mask);

    const int n16 = (int)(NELEM / 8);
    // Q scale folds softmax 1/sqrt(D) and log2(e): exp(s) == exp2(s*log2e)
    const float qscale = 0.125f * 1.44269504088896340736f;
    cvt_split<<<(n16 + 255) / 256, 256>>>((const float4*)q, qh, ql, qscale, n16);
    cvt_split<<<(n16 + 255) / 256, 256>>>((const float4*)k, kh, kl, 1.0f, n16);
    cvt_split<<<(n16 + 255) / 256, 256>>>((const float4*)v, vh, vl, 1.0f, n16);

    cudaFuncSetAttribute(fa_mma, cudaFuncAttributeMaxDynamicSharedMemorySize, SMEM_BYTES);
    dim3 grid(TDIM / BQ, BH);
    fa_mma<<<grid, NTH, SMEM_BYTES>>>(out);
}

// round 8
// speedup vs baseline: 1.1070x; 1.1070x over previous
#include <cuda_runtime.h>
#include <cuda_bf16.h>
#include <cstdint>

#define TDIM 2048
#define DDIM 64
#define BH 32
#define BQ 128
#define BK 64
#define NTH 512
#define KTILES (TDIM / BK)

// smem layout (bytes)
#define QH_OFF 0
#define QL_OFF 16384
#define PH_OFF 32768
#define PL_OFF 49152
#define KV_OFF 65536
#define KV_STAGE 32768
#define SMEM_BYTES (KV_OFF + 2 * KV_STAGE)   // 128 KB

#define NELEM ((size_t)BH * TDIM * DDIM)

__device__ unsigned int g_maskbits[(size_t)TDIM * TDIM / 32];  // 512 KB
__device__ uint4 g_qh[NELEM / 8], g_ql[NELEM / 8];
__device__ uint4 g_kh[NELEM / 8], g_kl[NELEM / 8];
__device__ uint4 g_vh[NELEM / 8], g_vl[NELEM / 8];

// ---------------- helpers ----------------
__device__ __forceinline__ uint32_t smem_u32(const void* p) {
    uint32_t a;
    asm("{ .reg .u64 t; cvta.to.shared.u64 t, %1; cvt.u32.u64 %0, t; }" : "=r"(a) : "l"(p));
    return a;
}
__device__ __forceinline__ uint32_t swz(uint32_t byte) {
    return byte ^ ((byte >> 3) & 0x70);
}
__device__ __forceinline__ void cp16(uint32_t dst, const void* src) {
    asm volatile("cp.async.cg.shared.global [%0], [%1], 16;" :: "r"(dst), "l"(src));
}
#define CP_COMMIT() asm volatile("cp.async.commit_group;" ::: "memory")
#define CP_WAIT(n)  asm volatile("cp.async.wait_group %0;" :: "n"(n) : "memory")

__device__ __forceinline__ void ldsm_x4(uint32_t (&r)[4], uint32_t addr) {
    asm volatile("ldmatrix.sync.aligned.m8n8.x4.shared.b16 {%0,%1,%2,%3}, [%4];"
                 : "=r"(r[0]), "=r"(r[1]), "=r"(r[2]), "=r"(r[3]) : "r"(addr));
}
__device__ __forceinline__ void ldsm_x4_t(uint32_t (&r)[4], uint32_t addr) {
    asm volatile("ldmatrix.sync.aligned.m8n8.x4.trans.shared.b16 {%0,%1,%2,%3}, [%4];"
                 : "=r"(r[0]), "=r"(r[1]), "=r"(r[2]), "=r"(r[3]) : "r"(addr));
}
__device__ __forceinline__ void mma16816(float (&c)[4], const uint32_t (&a)[4],
                                         uint32_t b0, uint32_t b1) {
    asm volatile(
        "mma.sync.aligned.m16n8k16.row.col.f32.bf16.bf16.f32 "
        "{%0,%1,%2,%3}, {%4,%5,%6,%7}, {%8,%9}, {%0,%1,%2,%3};"
        : "+f"(c[0]), "+f"(c[1]), "+f"(c[2]), "+f"(c[3])
        : "r"(a[0]), "r"(a[1]), "r"(a[2]), "r"(a[3]), "r"(b0), "r"(b1));
}
__device__ __forceinline__ float ex2f(float x) {
    float r;
    asm("ex2.approx.f32 %0, %1;" : "=f"(r) : "f"(x));
    return r;
}
__device__ __forceinline__ uint32_t pack_bf16x2(float x, float y) {
    __nv_bfloat16 hx = __float2bfloat16(x), hy = __float2bfloat16(y);
    return ((uint32_t)__bfloat16_as_ushort(hy) << 16) | __bfloat16_as_ushort(hx);
}
__device__ __forceinline__ void cvt_pair_store(char* smem, uint32_t hi_off, uint32_t lo_off,
                                               uint32_t byte, float x, float y) {
    __nv_bfloat16 hx = __float2bfloat16(x), hy = __float2bfloat16(y);
    float rx = x - __bfloat162float(hx), ry = y - __bfloat162float(hy);
    uint32_t sw = swz(byte);
    *(uint32_t*)(smem + hi_off + sw) =
        ((uint32_t)__bfloat16_as_ushort(hy) << 16) | __bfloat16_as_ushort(hx);
    *(uint32_t*)(smem + lo_off + sw) = pack_bf16x2(rx, ry);
}

// ---------------- prepass kernels ----------------
__global__ void pack_mask(const int* __restrict__ m) {
    int w = blockIdx.x * blockDim.x + threadIdx.x;
    if (w >= (TDIM * TDIM) / 32) return;
    const int4* p = (const int4*)(m + (size_t)w * 32);
    unsigned int bits = 0;
    #pragma unroll
    for (int i = 0; i < 8; ++i) {
        int4 v = p[i];
        bits |= (unsigned)(v.x != 0) << (i * 4);
        bits |= (unsigned)(v.y != 0) << (i * 4 + 1);
        bits |= (unsigned)(v.z != 0) << (i * 4 + 2);
        bits |= (unsigned)(v.w != 0) << (i * 4 + 3);
    }
    g_maskbits[w] = bits;
}

__global__ void cvt_split(const float4* __restrict__ src, uint4* __restrict__ hi,
                          uint4* __restrict__ lo, float scale, int n16) {
    int i = blockIdx.x * blockDim.x + threadIdx.x;
    if (i >= n16) return;
    float4 a = src[2 * i], b = src[2 * i + 1];
    a.x *= scale; a.y *= scale; a.z *= scale; a.w *= scale;
    b.x *= scale; b.y *= scale; b.z *= scale; b.w *= scale;
    __nv_bfloat16 h[8] = {
        __float2bfloat16(a.x), __float2bfloat16(a.y), __float2bfloat16(a.z), __float2bfloat16(a.w),
        __float2bfloat16(b.x), __float2bfloat16(b.y), __float2bfloat16(b.z), __float2bfloat16(b.w)};
    uint4 hw, lw;
    hw.x = ((uint32_t)__bfloat16_as_ushort(h[1]) << 16) | __bfloat16_as_ushort(h[0]);
    hw.y = ((uint32_t)__bfloat16_as_ushort(h[3]) << 16) | __bfloat16_as_ushort(h[2]);
    hw.z = ((uint32_t)__bfloat16_as_ushort(h[5]) << 16) | __bfloat16_as_ushort(h[4]);
    hw.w = ((uint32_t)__bfloat16_as_ushort(h[7]) << 16) | __bfloat16_as_ushort(h[6]);
    lw.x = pack_bf16x2(a.x - __bfloat162float(h[0]), a.y - __bfloat162float(h[1]));
    lw.y = pack_bf16x2(a.z - __bfloat162float(h[2]), a.w - __bfloat162float(h[3]));
    lw.z = pack_bf16x2(b.x - __bfloat162float(h[4]), b.y - __bfloat162float(h[5]));
    lw.w = pack_bf16x2(b.z - __bfloat162float(h[6]), b.w - __bfloat162float(h[7]));
    hi[i] = hw;
    lo[i] = lw;
}

// ------------- main kernel: 16 warps, d-split warp pairs -------------
__global__ __launch_bounds__(NTH, 1)
void fa_mma(float* __restrict__ go)
{
    extern __shared__ char smem[];
    const uint32_t sb = smem_u32(smem);
    const int tid = threadIdx.x;
    const int lane = tid & 31, wid = tid >> 5;
    const int ch = wid & 1;           // n-half (S) / d-half (O) selector
    const int pr = wid >> 1;          // warp-pair id -> 16-row Q band
    const int m0 = pr * 16;
    const int bh = blockIdx.y;
    const int q0 = blockIdx.x * BQ;

    const size_t row_bytes = 128;
    const char* gqh = (const char*)g_qh + ((size_t)bh * TDIM + q0) * row_bytes;
    const char* gql = (const char*)g_ql + ((size_t)bh * TDIM + q0) * row_bytes;
    const char* gkh0 = (const char*)g_kh + (size_t)bh * TDIM * row_bytes;
    const char* gkl0 = (const char*)g_kl + (size_t)bh * TDIM * row_bytes;
    const char* gvh0 = (const char*)g_vh + (size_t)bh * TDIM * row_bytes;
    const char* gvl0 = (const char*)g_vl + (size_t)bh * TDIM * row_bytes;
    float* ob = go + (size_t)bh * TDIM * DDIM;

    // ---- prologue: async-load Q tile (hi/lo) ----
    #pragma unroll
    for (int j = 0; j < 2; ++j) {
        uint32_t byte = (tid + j * NTH) * 16;
        uint32_t sw = swz(byte);
        cp16(sb + QH_OFF + sw, gqh + byte);
        cp16(sb + QL_OFF + sw, gql + byte);
    }
    CP_COMMIT();
    // ---- K/V tile 0 into stage 0 ----
    {
        uint32_t byte = tid * 16;
        uint32_t sw = swz(byte);
        uint32_t base = sb + KV_OFF;
        cp16(base + sw,         gkh0 + byte);
        cp16(base + 8192 + sw,  gkl0 + byte);
        cp16(base + 16384 + sw, gvh0 + byte);
        cp16(base + 24576 + sw, gvl0 + byte);
    }
    CP_COMMIT();
    CP_WAIT(0);
    __syncthreads();

    // fragment address pieces
    const uint32_t arow  = m0 + ((lane >> 3) & 1) * 8 + (lane & 7);
    const uint32_t acol0 = (lane >> 4) * 16;
    const uint32_t brow  = ((lane >> 4) & 1) * 8 + (lane & 7);
    const uint32_t bcol0 = ((lane >> 3) & 1) * 16;
    const uint32_t trow0 = ((lane >> 3) & 1) * 8 + (lane & 7);
    const uint32_t tcol0 = ((lane >> 4) & 1) * 16;

    // ---- preload Q fragments (reused across all K-tiles) ----
    uint32_t aQh[4][4], aQl[4][4];
    #pragma unroll
    for (int ks = 0; ks < 4; ++ks) {
        uint32_t sw = swz(arow * 128 + ks * 32 + acol0);
        ldsm_x4(aQh[ks], sb + QH_OFF + sw);
        ldsm_x4(aQl[ks], sb + QL_OFF + sw);
    }

    float oreg[4][4];                 // warp's 16 rows x 32 d-cols
    #pragma unroll
    for (int i = 0; i < 4; ++i)
        #pragma unroll
        for (int j = 0; j < 4; ++j) oreg[i][j] = 0.f;
    float lsum0 = 0.f, lsum1 = 0.f;

    const int g  = lane >> 2;
    const int tq = lane & 3;
    const int r0loc = m0 + g;

    for (int kt = 0; kt < KTILES; ++kt) {
        if (kt > 0) {
            CP_WAIT(0);
            __syncthreads();          // tile kt resident + last tile's P consumed
        }

        // warp's 32-col mask words (early independent LDG)
        uint32_t mw0 = g_maskbits[(size_t)(q0 + r0loc) * (TDIM / 32) + kt * 2 + ch];
        uint32_t mw1 = g_maskbits[(size_t)(q0 + r0loc + 8) * (TDIM / 32) + kt * 2 + ch];

        const uint32_t kvb = sb + KV_OFF + (kt & 1) * KV_STAGE;
        const uint32_t khb = kvb, klb = kvb + 8192, vhb = kvb + 16384, vlb = kvb + 24576;

        // ---- S = Q K^T over this warp's 32 n-cols (3-term bf16 emulation) ----
        float s[4][4];
        #pragma unroll
        for (int i = 0; i < 4; ++i)
            #pragma unroll
            for (int j = 0; j < 4; ++j) s[i][j] = 0.f;

        #pragma unroll
        for (int ks = 0; ks < 4; ++ks) {
            uint32_t bHf[2][4], bLf[2][4];
            #pragma unroll
            for (int np = 0; np < 2; ++np) {
                uint32_t nglob = ch * 2 + np;
                uint32_t sw = swz((nglob * 16 + brow) * 128 + ks * 32 + bcol0);
                ldsm_x4(bHf[np], khb + sw);
                ldsm_x4(bLf[np], klb + sw);
            }
            #pragma unroll
            for (int np = 0; np < 2; ++np) {
                mma16816(s[2 * np],     aQh[ks], bHf[np][0], bHf[np][1]);
                mma16816(s[2 * np + 1], aQh[ks], bHf[np][2], bHf[np][3]);
            }
            #pragma unroll
            for (int np = 0; np < 2; ++np) {
                mma16816(s[2 * np],     aQh[ks], bLf[np][0], bLf[np][1]);
                mma16816(s[2 * np + 1], aQh[ks], bLf[np][2], bLf[np][3]);
            }
            #pragma unroll
            for (int np = 0; np < 2; ++np) {
                mma16816(s[2 * np],     aQl[ks], bHf[np][0], bHf[np][1]);
                mma16816(s[2 * np + 1], aQl[ks], bHf[np][2], bHf[np][3]);
            }
        }

        // ---- mask + exp2 + write P (own 32 cols) ----
        #pragma unroll
        for (int j = 0; j < 4; ++j) {
            int c = (j >> 1) * 16 + (j & 1) * 8 + tq * 2;   // within warp's 32 cols
            float p0 = ((mw0 >> c) & 1u)       ? 0.f : ex2f(s[j][0]);
            float p1 = ((mw0 >> (c + 1)) & 1u) ? 0.f : ex2f(s[j][1]);
            float p2 = ((mw1 >> c) & 1u)       ? 0.f : ex2f(s[j][2]);
            float p3 = ((mw1 >> (c + 1)) & 1u) ? 0.f : ex2f(s[j][3]);
            lsum0 += p0 + p1;
            lsum1 += p2 + p3;
            uint32_t colg = ch * 32 + c;
            cvt_pair_store(smem, PH_OFF, PL_OFF, (uint32_t)(r0loc * 128 + colg * 2), p0, p1);
            cvt_pair_store(smem, PH_OFF, PL_OFF, (uint32_t)((r0loc + 8) * 128 + colg * 2), p2, p3);
        }
        __syncthreads();   // pair's P halves visible

        // ---- prefetch next tile (overlaps PV below) ----
        if (kt + 1 < KTILES) {
            const size_t toff = (size_t)(kt + 1) * BK * row_bytes;
            uint32_t base = sb + KV_OFF + ((kt + 1) & 1) * KV_STAGE;
            uint32_t byte = tid * 16;
            uint32_t sw = swz(byte);
            cp16(base + sw,         gkh0 + toff + byte);
            cp16(base + 8192 + sw,  gkl0 + toff + byte);
            cp16(base + 16384 + sw, gvh0 + toff + byte);
            cp16(base + 24576 + sw, gvl0 + toff + byte);
            CP_COMMIT();
        }

        // ---- O += P V over full k, own 32 d-cols (3-term) ----
        #pragma unroll
        for (int ks = 0; ks < 4; ++ks) {
            uint32_t swA = swz(arow * 128 + ks * 32 + acol0);
            uint32_t aPh[4], aPl[4];
            ldsm_x4(aPh, sb + PH_OFF + swA);
            ldsm_x4(aPl, sb + PL_OFF + swA);
            uint32_t bHf[2][4], bLf[2][4];
            #pragma unroll
            for (int np = 0; np < 2; ++np) {
                uint32_t swB = swz((ks * 16 + trow0) * 128 + ch * 64 + np * 32 + tcol0);
                ldsm_x4_t(bHf[np], vhb + swB);
                ldsm_x4_t(bLf[np], vlb + swB);
            }
            #pragma unroll
            for (int np = 0; np < 2; ++np) {
                mma16816(oreg[2 * np],     aPh, bHf[np][0], bHf[np][1]);
                mma16816(oreg[2 * np + 1], aPh, bHf[np][2], bHf[np][3]);
            }
            #pragma unroll
            for (int np = 0; np < 2; ++np) {
                mma16816(oreg[2 * np],     aPh, bLf[np][0], bLf[np][1]);
                mma16816(oreg[2 * np + 1], aPh, bLf[np][2], bLf[np][3]);
            }
            #pragma unroll
            for (int np = 0; np < 2; ++np) {
                mma16816(oreg[2 * np],     aPl, bHf[np][0], bHf[np][1]);
                mma16816(oreg[2 * np + 1], aPl, bHf[np][2], bHf[np][3]);
            }
        }
    }

    // ---- epilogue: pair-sum lsum, normalize own O block ----
    #pragma unroll
    for (int off = 1; off <= 2; off <<= 1) {
        lsum0 += __shfl_xor_sync(0xffffffffu, lsum0, off);
        lsum1 += __shfl_xor_sync(0xffffffffu, lsum1, off);
    }
    float* lred = (float*)(smem + QH_OFF);   // 256 floats (Q smem no longer needed)
    __syncthreads();
    lred[ch * 128 + r0loc]     = lsum0;
    lred[ch * 128 + r0loc + 8] = lsum1;
    __syncthreads();
    float inv0 = 1.f / (lred[r0loc]     + lred[128 + r0loc]);
    float inv1 = 1.f / (lred[r0loc + 8] + lred[128 + r0loc + 8]);

    float* orow0 = ob + (size_t)(q0 + r0loc) * DDIM + ch * 32;
    float* orow1 = ob + (size_t)(q0 + r0loc + 8) * DDIM + ch * 32;
    #pragma unroll
    for (int ng = 0; ng < 4; ++ng) {
        int c = (ng >> 1) * 16 + (ng & 1) * 8 + tq * 2;
        *(float2*)(orow0 + c) = make_float2(oreg[ng][0] * inv0, oreg[ng][1] * inv0);
        *(float2*)(orow1 + c) = make_float2(oreg[ng][2] * inv1, oreg[ng][3] * inv1);
    }
}

extern "C" void kernel_launch(void* const* d_in, const int* in_sizes, int n_in,
                              void* d_out, int out_size) {
    const float* q = (const float*)d_in[0];
    const float* k = (const float*)d_in[1];
    const float* v = (const float*)d_in[2];
    const int* mask = (const int*)d_in[3];
    float* out = (float*)d_out;

    uint4 *qh, *ql, *kh, *kl, *vh, *vl;
    cudaGetSymbolAddress((void**)&qh, g_qh);
    cudaGetSymbolAddress((void**)&ql, g_ql);
    cudaGetSymbolAddress((void**)&kh, g_kh);
    cudaGetSymbolAddress((void**)&kl, g_kl);
    cudaGetSymbolAddress((void**)&vh, g_vh);
    cudaGetSymbolAddress((void**)&vl, g_vl);

    pack_mask<<<(TDIM * TDIM / 32 + 255) / 256, 256>>>(mask);

    const int n16 = (int)(NELEM / 8);
    // Q scale folds softmax 1/sqrt(D) and log2(e): exp(s) == exp2(s*log2e)
    const float qscale = 0.125f * 1.44269504088896340736f;
    cvt_split<<<(n16 + 255) / 256, 256>>>((const float4*)q, qh, ql, qscale, n16);
    cvt_split<<<(n16 + 255) / 256, 256>>>((const float4*)k, kh, kl, 1.0f, n16);
    cvt_split<<<(n16 + 255) / 256, 256>>>((const float4*)v, vh, vl, 1.0f, n16);

    cudaFuncSetAttribute(fa_mma, cudaFuncAttributeMaxDynamicSharedMemorySize, SMEM_BYTES);
    dim3 grid(TDIM / BQ, BH);
    fa_mma<<<grid, NTH, SMEM_BYTES>>>(out);
}

// round 9
// speedup vs baseline: 1.2749x; 1.1517x over previous
#include <cuda_runtime.h>
#include <cuda_bf16.h>
#include <cstdint>

#define TDIM 2048
#define DDIM 64
#define BH 32
#define BQ 128
#define BK 64
#define NTH 256
#define KTILES (TDIM / BK)

// smem layout (bytes): P hi/lo [128][128B], KV double-buffered stages
#define PH_OFF 0
#define PL_OFF 16384
#define KV_OFF 32768
#define KV_STAGE 32768
#define SMEM_BYTES (KV_OFF + 2 * KV_STAGE)   // 96 KB -> 2 CTAs/SM

#define NELEM ((size_t)BH * TDIM * DDIM)

__device__ unsigned int g_maskbits[(size_t)TDIM * TDIM / 32];  // 512 KB
__device__ uint4 g_qh[NELEM / 8], g_ql[NELEM / 8];
__device__ uint4 g_kh[NELEM / 8], g_kl[NELEM / 8];
__device__ uint4 g_vh[NELEM / 8], g_vl[NELEM / 8];

// ---------------- helpers ----------------
__device__ __forceinline__ uint32_t smem_u32(const void* p) {
    uint32_t a;
    asm("{ .reg .u64 t; cvta.to.shared.u64 t, %1; cvt.u32.u64 %0, t; }" : "=r"(a) : "l"(p));
    return a;
}
__device__ __forceinline__ uint32_t swz(uint32_t byte) {
    return byte ^ ((byte >> 3) & 0x70);
}
__device__ __forceinline__ void cp16(uint32_t dst, const void* src) {
    asm volatile("cp.async.cg.shared.global [%0], [%1], 16;" :: "r"(dst), "l"(src));
}
#define CP_COMMIT() asm volatile("cp.async.commit_group;" ::: "memory")
#define CP_WAIT(n)  asm volatile("cp.async.wait_group %0;" :: "n"(n) : "memory")

__device__ __forceinline__ void ldsm_x4(uint32_t (&r)[4], uint32_t addr) {
    asm volatile("ldmatrix.sync.aligned.m8n8.x4.shared.b16 {%0,%1,%2,%3}, [%4];"
                 : "=r"(r[0]), "=r"(r[1]), "=r"(r[2]), "=r"(r[3]) : "r"(addr));
}
__device__ __forceinline__ void ldsm_x4_t(uint32_t (&r)[4], uint32_t addr) {
    asm volatile("ldmatrix.sync.aligned.m8n8.x4.trans.shared.b16 {%0,%1,%2,%3}, [%4];"
                 : "=r"(r[0]), "=r"(r[1]), "=r"(r[2]), "=r"(r[3]) : "r"(addr));
}
__device__ __forceinline__ void mma16816(float (&c)[4], const uint32_t (&a)[4],
                                         uint32_t b0, uint32_t b1) {
    asm volatile(
        "mma.sync.aligned.m16n8k16.row.col.f32.bf16.bf16.f32 "
        "{%0,%1,%2,%3}, {%4,%5,%6,%7}, {%8,%9}, {%0,%1,%2,%3};"
        : "+f"(c[0]), "+f"(c[1]), "+f"(c[2]), "+f"(c[3])
        : "r"(a[0]), "r"(a[1]), "r"(a[2]), "r"(a[3]), "r"(b0), "r"(b1));
}
__device__ __forceinline__ float ex2f(float x) {
    float r;
    asm("ex2.approx.f32 %0, %1;" : "=f"(r) : "f"(x));
    return r;
}
__device__ __forceinline__ uint32_t pack_bf16x2(float x, float y) {
    __nv_bfloat16 hx = __float2bfloat16(x), hy = __float2bfloat16(y);
    return ((uint32_t)__bfloat16_as_ushort(hy) << 16) | __bfloat16_as_ushort(hx);
}
__device__ __forceinline__ void cvt_pair_store(char* smem, uint32_t hi_off, uint32_t lo_off,
                                               uint32_t byte, float x, float y) {
    __nv_bfloat16 hx = __float2bfloat16(x), hy = __float2bfloat16(y);
    float rx = x - __bfloat162float(hx), ry = y - __bfloat162float(hy);
    uint32_t sw = swz(byte);
    *(uint32_t*)(smem + hi_off + sw) =
        ((uint32_t)__bfloat16_as_ushort(hy) << 16) | __bfloat16_as_ushort(hx);
    *(uint32_t*)(smem + lo_off + sw) = pack_bf16x2(rx, ry);
}

// ---------------- prepass kernels ----------------
__global__ void pack_mask(const int* __restrict__ m) {
    int w = blockIdx.x * blockDim.x + threadIdx.x;
    if (w >= (TDIM * TDIM) / 32) return;
    const int4* p = (const int4*)(m + (size_t)w * 32);
    unsigned int bits = 0;
    #pragma unroll
    for (int i = 0; i < 8; ++i) {
        int4 v = p[i];
        bits |= (unsigned)(v.x != 0) << (i * 4);
        bits |= (unsigned)(v.y != 0) << (i * 4 + 1);
        bits |= (unsigned)(v.z != 0) << (i * 4 + 2);
        bits |= (unsigned)(v.w != 0) << (i * 4 + 3);
    }
    g_maskbits[w] = bits;
}

__global__ void cvt_split(const float4* __restrict__ src, uint4* __restrict__ hi,
                          uint4* __restrict__ lo, float scale, int n16) {
    int i = blockIdx.x * blockDim.x + threadIdx.x;
    if (i >= n16) return;
    float4 a = src[2 * i], b = src[2 * i + 1];
    a.x *= scale; a.y *= scale; a.z *= scale; a.w *= scale;
    b.x *= scale; b.y *= scale; b.z *= scale; b.w *= scale;
    __nv_bfloat16 h[8] = {
        __float2bfloat16(a.x), __float2bfloat16(a.y), __float2bfloat16(a.z), __float2bfloat16(a.w),
        __float2bfloat16(b.x), __float2bfloat16(b.y), __float2bfloat16(b.z), __float2bfloat16(b.w)};
    uint4 hw, lw;
    hw.x = ((uint32_t)__bfloat16_as_ushort(h[1]) << 16) | __bfloat16_as_ushort(h[0]);
    hw.y = ((uint32_t)__bfloat16_as_ushort(h[3]) << 16) | __bfloat16_as_ushort(h[2]);
    hw.z = ((uint32_t)__bfloat16_as_ushort(h[5]) << 16) | __bfloat16_as_ushort(h[4]);
    hw.w = ((uint32_t)__bfloat16_as_ushort(h[7]) << 16) | __bfloat16_as_ushort(h[6]);
    lw.x = pack_bf16x2(a.x - __bfloat162float(h[0]), a.y - __bfloat162float(h[1]));
    lw.y = pack_bf16x2(a.z - __bfloat162float(h[2]), a.w - __bfloat162float(h[3]));
    lw.z = pack_bf16x2(b.x - __bfloat162float(h[4]), b.y - __bfloat162float(h[5]));
    lw.w = pack_bf16x2(b.z - __bfloat162float(h[6]), b.w - __bfloat162float(h[7]));
    hi[i] = hw;
    lo[i] = lw;
}

// -------- main kernel: 8 warps, warp-private P, 2 CTAs/SM --------
__global__ __launch_bounds__(NTH, 2)
void fa_mma(float* __restrict__ go)
{
    extern __shared__ char smem[];
    const uint32_t sb = smem_u32(smem);
    const int tid = threadIdx.x;
    const int lane = tid & 31, wid = tid >> 5;
    const int bh = blockIdx.y;
    const int q0 = blockIdx.x * BQ;
    const int m0 = wid * 16;

    const size_t row_bytes = 128;
    const char* gqh = (const char*)g_qh + ((size_t)bh * TDIM + q0) * row_bytes;
    const char* gql = (const char*)g_ql + ((size_t)bh * TDIM + q0) * row_bytes;
    const char* gkh0 = (const char*)g_kh + (size_t)bh * TDIM * row_bytes;
    const char* gkl0 = (const char*)g_kl + (size_t)bh * TDIM * row_bytes;
    const char* gvh0 = (const char*)g_vh + (size_t)bh * TDIM * row_bytes;
    const char* gvl0 = (const char*)g_vl + (size_t)bh * TDIM * row_bytes;
    float* ob = go + (size_t)bh * TDIM * DDIM;

    // ---- K/V tile 0 into stage 0 (8 cp16/thread) ----
    #pragma unroll
    for (int j = 0; j < 2; ++j) {
        uint32_t byte = (tid + j * NTH) * 16;
        uint32_t sw = swz(byte);
        uint32_t base = sb + KV_OFF;
        cp16(base + sw,         gkh0 + byte);
        cp16(base + 8192 + sw,  gkl0 + byte);
        cp16(base + 16384 + sw, gvh0 + byte);
        cp16(base + 24576 + sw, gvl0 + byte);
    }
    CP_COMMIT();

    const int g  = lane >> 2;
    const int tq = lane & 3;
    const int r0loc = m0 + g;

    // ---- Q fragments straight from global (A-frag layout is 2 consecutive bf16) ----
    uint32_t aQh[4][4], aQl[4][4];
    #pragma unroll
    for (int ks = 0; ks < 4; ++ks) {
        uint32_t cb = ks * 32 + tq * 4;
        const char* r0h = gqh + (size_t)r0loc * 128;
        const char* r1h = gqh + (size_t)(r0loc + 8) * 128;
        const char* r0l = gql + (size_t)r0loc * 128;
        const char* r1l = gql + (size_t)(r0loc + 8) * 128;
        aQh[ks][0] = *(const uint32_t*)(r0h + cb);
        aQh[ks][1] = *(const uint32_t*)(r1h + cb);
        aQh[ks][2] = *(const uint32_t*)(r0h + cb + 16);
        aQh[ks][3] = *(const uint32_t*)(r1h + cb + 16);
        aQl[ks][0] = *(const uint32_t*)(r0l + cb);
        aQl[ks][1] = *(const uint32_t*)(r1l + cb);
        aQl[ks][2] = *(const uint32_t*)(r0l + cb + 16);
        aQl[ks][3] = *(const uint32_t*)(r1l + cb + 16);
    }

    // fragment address pieces (B operands via ldmatrix)
    const uint32_t arow  = m0 + ((lane >> 3) & 1) * 8 + (lane & 7);
    const uint32_t acol0 = (lane >> 4) * 16;
    const uint32_t brow  = ((lane >> 4) & 1) * 8 + (lane & 7);
    const uint32_t bcol0 = ((lane >> 3) & 1) * 16;
    const uint32_t trow0 = ((lane >> 3) & 1) * 8 + (lane & 7);
    const uint32_t tcol0 = ((lane >> 4) & 1) * 16;

    float oreg[8][4];
    #pragma unroll
    for (int i = 0; i < 8; ++i)
        #pragma unroll
        for (int j = 0; j < 4; ++j) oreg[i][j] = 0.f;
    float lsum0 = 0.f, lsum1 = 0.f;

    CP_WAIT(0);
    __syncthreads();

    for (int kt = 0; kt < KTILES; ++kt) {
        // ---- prefetch next tile into alternate stage ----
        if (kt + 1 < KTILES) {
            const size_t toff = (size_t)(kt + 1) * BK * row_bytes;
            uint32_t base = sb + KV_OFF + ((kt + 1) & 1) * KV_STAGE;
            #pragma unroll
            for (int j = 0; j < 2; ++j) {
                uint32_t byte = (tid + j * NTH) * 16;
                uint32_t sw = swz(byte);
                cp16(base + sw,         gkh0 + toff + byte);
                cp16(base + 8192 + sw,  gkl0 + toff + byte);
                cp16(base + 16384 + sw, gvh0 + toff + byte);
                cp16(base + 24576 + sw, gvl0 + toff + byte);
            }
            CP_COMMIT();
        }

        // early mask fetch
        unsigned long long mw0 =
            *(const unsigned long long*)(g_maskbits + (size_t)(q0 + r0loc) * (TDIM / 32) + kt * 2);
        unsigned long long mw1 =
            *(const unsigned long long*)(g_maskbits + (size_t)(q0 + r0loc + 8) * (TDIM / 32) + kt * 2);

        const uint32_t kvb = sb + KV_OFF + (kt & 1) * KV_STAGE;
        const uint32_t khb = kvb, klb = kvb + 8192, vhb = kvb + 16384, vlb = kvb + 24576;

        // ---- S = Q K^T (3-term bf16 emulation) ----
        float s[8][4];
        #pragma unroll
        for (int i = 0; i < 8; ++i)
            #pragma unroll
            for (int j = 0; j < 4; ++j) s[i][j] = 0.f;

        #pragma unroll
        for (int ks = 0; ks < 4; ++ks) {
            #pragma unroll
            for (int np = 0; np < 4; ++np) {
                uint32_t sw = swz((np * 16 + brow) * 128 + ks * 32 + bcol0);
                uint32_t bHf[4], bLf[4];
                ldsm_x4(bHf, khb + sw);
                ldsm_x4(bLf, klb + sw);
                mma16816(s[2 * np],     aQh[ks], bHf[0], bHf[1]);
                mma16816(s[2 * np + 1], aQh[ks], bHf[2], bHf[3]);
                mma16816(s[2 * np],     aQh[ks], bLf[0], bLf[1]);
                mma16816(s[2 * np + 1], aQh[ks], bLf[2], bLf[3]);
                mma16816(s[2 * np],     aQl[ks], bHf[0], bHf[1]);
                mma16816(s[2 * np + 1], aQl[ks], bHf[2], bHf[3]);
            }
        }

        // ---- mask + exp2 + write P (warp-private rows) ----
        #pragma unroll
        for (int ng = 0; ng < 8; ++ng) {
            int c = ng * 8 + tq * 2;
            float p0 = ((mw0 >> c) & 1ULL)       ? 0.f : ex2f(s[ng][0]);
            float p1 = ((mw0 >> (c + 1)) & 1ULL) ? 0.f : ex2f(s[ng][1]);
            float p2 = ((mw1 >> c) & 1ULL)       ? 0.f : ex2f(s[ng][2]);
            float p3 = ((mw1 >> (c + 1)) & 1ULL) ? 0.f : ex2f(s[ng][3]);
            lsum0 += p0 + p1;
            lsum1 += p2 + p3;
            cvt_pair_store(smem, PH_OFF, PL_OFF, (uint32_t)(r0loc * 128 + c * 2), p0, p1);
            cvt_pair_store(smem, PH_OFF, PL_OFF, (uint32_t)((r0loc + 8) * 128 + c * 2), p2, p3);
        }
        __syncwarp();

        // ---- O += P V (3-term), V via ldmatrix.trans ----
        #pragma unroll
        for (int ks = 0; ks < 4; ++ks) {
            uint32_t swA = swz(arow * 128 + ks * 32 + acol0);
            uint32_t aPh[4], aPl[4];
            ldsm_x4(aPh, sb + PH_OFF + swA);
            ldsm_x4(aPl, sb + PL_OFF + swA);
            #pragma unroll
            for (int np = 0; np < 4; ++np) {
                uint32_t swB = swz((ks * 16 + trow0) * 128 + np * 32 + tcol0);
                uint32_t bHf[4], bLf[4];
                ldsm_x4_t(bHf, vhb + swB);
                ldsm_x4_t(bLf, vlb + swB);
                mma16816(oreg[2 * np],     aPh, bHf[0], bHf[1]);
                mma16816(oreg[2 * np + 1], aPh, bHf[2], bHf[3]);
                mma16816(oreg[2 * np],     aPh, bLf[0], bLf[1]);
                mma16816(oreg[2 * np + 1], aPh, bLf[2], bLf[3]);
                mma16816(oreg[2 * np],     aPl, bHf[0], bHf[1]);
                mma16816(oreg[2 * np + 1], aPl, bHf[2], bHf[3]);
            }
        }

        // next tile resident + everyone done with this stage
        if (kt + 1 < KTILES) CP_WAIT(0);
        __syncthreads();
    }

    // ---- epilogue ----
    #pragma unroll
    for (int off = 1; off <= 2; off <<= 1) {
        lsum0 += __shfl_xor_sync(0xffffffffu, lsum0, off);
        lsum1 += __shfl_xor_sync(0xffffffffu, lsum1, off);
    }
    float inv0 = 1.f / lsum0;
    float inv1 = 1.f / lsum1;

    float* orow0 = ob + (size_t)(q0 + r0loc) * DDIM;
    float* orow1 = ob + (size_t)(q0 + r0loc + 8) * DDIM;
    #pragma unroll
    for (int ng = 0; ng < 8; ++ng) {
        int c = ng * 8 + tq * 2;
        *(float2*)(orow0 + c) = make_float2(oreg[ng][0] * inv0, oreg[ng][1] * inv0);
        *(float2*)(orow1 + c) = make_float2(oreg[ng][2] * inv1, oreg[ng][3] * inv1);
    }
}

extern "C" void kernel_launch(void* const* d_in, const int* in_sizes, int n_in,
                              void* d_out, int out_size) {
    const float* q = (const float*)d_in[0];
    const float* k = (const float*)d_in[1];
    const float* v = (const float*)d_in[2];
    const int* mask = (const int*)d_in[3];
    float* out = (float*)d_out;

    uint4 *qh, *ql, *kh, *kl, *vh, *vl;
    cudaGetSymbolAddress((void**)&qh, g_qh);
    cudaGetSymbolAddress((void**)&ql, g_ql);
    cudaGetSymbolAddress((void**)&kh, g_kh);
    cudaGetSymbolAddress((void**)&kl, g_kl);
    cudaGetSymbolAddress((void**)&vh, g_vh);
    cudaGetSymbolAddress((void**)&vl, g_vl);

    pack_mask<<<(TDIM * TDIM / 32 + 255) / 256, 256>>>(mask);

    const int n16 = (int)(NELEM / 8);
    // Q scale folds softmax 1/sqrt(D) and log2(e): exp(s) == exp2(s*log2e)
    const float qscale = 0.125f * 1.44269504088896340736f;
    cvt_split<<<(n16 + 255) / 256, 256>>>((const float4*)q, qh, ql, qscale, n16);
    cvt_split<<<(n16 + 255) / 256, 256>>>((const float4*)k, kh, kl, 1.0f, n16);
    cvt_split<<<(n16 + 255) / 256, 256>>>((const float4*)v, vh, vl, 1.0f, n16);

    cudaFuncSetAttribute(fa_mma, cudaFuncAttributeMaxDynamicSharedMemorySize, SMEM_BYTES);
    dim3 grid(TDIM / BQ, BH);
    fa_mma<<<grid, NTH, SMEM_BYTES>>>(out);
}

// round 10
// speedup vs baseline: 1.6476x; 1.2923x over previous
#include <cuda_runtime.h>
#include <cuda_fp16.h>
#include <cstdint>

#define TDIM 2048
#define DDIM 64
#define BH 32
#define BQ 128
#define BK 64
#define NTH 256
#define KTILES (TDIM / BK)

// smem layout (bytes): P fp16 [128][128B], KV double-buffered stages {KH,KL,VH} 8KB each
#define PH_OFF 0
#define KV_OFF 16384
#define KV_STAGE 24576
#define SMEM_BYTES (KV_OFF + 2 * KV_STAGE)   // 64 KB -> 2 CTAs/SM

#define NELEM ((size_t)BH * TDIM * DDIM)

__device__ unsigned int g_maskbits[(size_t)TDIM * TDIM / 32];  // 512 KB
__device__ uint4 g_qh[NELEM / 8], g_ql[NELEM / 8];
__device__ uint4 g_kh[NELEM / 8], g_kl[NELEM / 8];
__device__ uint4 g_vh[NELEM / 8];

// ---------------- helpers ----------------
__device__ __forceinline__ uint32_t smem_u32(const void* p) {
    uint32_t a;
    asm("{ .reg .u64 t; cvta.to.shared.u64 t, %1; cvt.u32.u64 %0, t; }" : "=r"(a) : "l"(p));
    return a;
}
__device__ __forceinline__ uint32_t swz(uint32_t byte) {
    return byte ^ ((byte >> 3) & 0x70);
}
__device__ __forceinline__ void cp16(uint32_t dst, const void* src) {
    asm volatile("cp.async.cg.shared.global [%0], [%1], 16;" :: "r"(dst), "l"(src));
}
#define CP_COMMIT() asm volatile("cp.async.commit_group;" ::: "memory")
#define CP_WAIT(n)  asm volatile("cp.async.wait_group %0;" :: "n"(n) : "memory")

__device__ __forceinline__ void ldsm_x4(uint32_t (&r)[4], uint32_t addr) {
    asm volatile("ldmatrix.sync.aligned.m8n8.x4.shared.b16 {%0,%1,%2,%3}, [%4];"
                 : "=r"(r[0]), "=r"(r[1]), "=r"(r[2]), "=r"(r[3]) : "r"(addr));
}
__device__ __forceinline__ void ldsm_x4_t(uint32_t (&r)[4], uint32_t addr) {
    asm volatile("ldmatrix.sync.aligned.m8n8.x4.trans.shared.b16 {%0,%1,%2,%3}, [%4];"
                 : "=r"(r[0]), "=r"(r[1]), "=r"(r[2]), "=r"(r[3]) : "r"(addr));
}
// fp16 MMA, fp32 accumulate
__device__ __forceinline__ void mma16816(float (&c)[4], const uint32_t (&a)[4],
                                         uint32_t b0, uint32_t b1) {
    asm volatile(
        "mma.sync.aligned.m16n8k16.row.col.f32.f16.f16.f32 "
        "{%0,%1,%2,%3}, {%4,%5,%6,%7}, {%8,%9}, {%0,%1,%2,%3};"
        : "+f"(c[0]), "+f"(c[1]), "+f"(c[2]), "+f"(c[3])
        : "r"(a[0]), "r"(a[1]), "r"(a[2]), "r"(a[3]), "r"(b0), "r"(b1));
}
__device__ __forceinline__ float ex2f(float x) {
    float r;
    asm("ex2.approx.f32 %0, %1;" : "=f"(r) : "f"(x));
    return r;
}
__device__ __forceinline__ uint32_t pack_h2(float x, float y) {
    __half hx = __float2half_rn(x), hy = __float2half_rn(y);
    return ((uint32_t)__half_as_ushort(hy) << 16) | __half_as_ushort(hx);
}

// ---------------- prepass kernels ----------------
__global__ void pack_mask(const int* __restrict__ m) {
    int w = blockIdx.x * blockDim.x + threadIdx.x;
    if (w >= (TDIM * TDIM) / 32) return;
    const int4* p = (const int4*)(m + (size_t)w * 32);
    unsigned int bits = 0;
    #pragma unroll
    for (int i = 0; i < 8; ++i) {
        int4 v = p[i];
        bits |= (unsigned)(v.x != 0) << (i * 4);
        bits |= (unsigned)(v.y != 0) << (i * 4 + 1);
        bits |= (unsigned)(v.z != 0) << (i * 4 + 2);
        bits |= (unsigned)(v.w != 0) << (i * 4 + 3);
    }
    g_maskbits[w] = bits;
}

// fp32 -> fp16 hi/lo split (8 elems/thread)
__global__ void cvt_split_f16(const float4* __restrict__ src, uint4* __restrict__ hi,
                              uint4* __restrict__ lo, float scale, int n16) {
    int i = blockIdx.x * blockDim.x + threadIdx.x;
    if (i >= n16) return;
    float4 a = src[2 * i], b = src[2 * i + 1];
    float e[8] = { a.x * scale, a.y * scale, a.z * scale, a.w * scale,
                   b.x * scale, b.y * scale, b.z * scale, b.w * scale };
    ushort hs[8], ls[8];
    #pragma unroll
    for (int j = 0; j < 8; ++j) {
        __half h = __float2half_rn(e[j]);
        __half l = __float2half_rn(e[j] - __half2float(h));
        hs[j] = __half_as_ushort(h);
        ls[j] = __half_as_ushort(l);
    }
    uint4 hw, lw;
    hw.x = ((uint32_t)hs[1] << 16) | hs[0];  hw.y = ((uint32_t)hs[3] << 16) | hs[2];
    hw.z = ((uint32_t)hs[5] << 16) | hs[4];  hw.w = ((uint32_t)hs[7] << 16) | hs[6];
    lw.x = ((uint32_t)ls[1] << 16) | ls[0];  lw.y = ((uint32_t)ls[3] << 16) | ls[2];
    lw.z = ((uint32_t)ls[5] << 16) | ls[4];  lw.w = ((uint32_t)ls[7] << 16) | ls[6];
    hi[i] = hw;
    lo[i] = lw;
}

// fp32 -> fp16 single (8 elems/thread)
__global__ void cvt_f16(const float4* __restrict__ src, uint4* __restrict__ dst, int n16) {
    int i = blockIdx.x * blockDim.x + threadIdx.x;
    if (i >= n16) return;
    float4 a = src[2 * i], b = src[2 * i + 1];
    uint4 w;
    w.x = pack_h2(a.x, a.y);  w.y = pack_h2(a.z, a.w);
    w.z = pack_h2(b.x, b.y);  w.w = pack_h2(b.z, b.w);
    dst[i] = w;
}

// -------- main kernel: 8 warps, warp-private P, 2 CTAs/SM, fp16 --------
__global__ __launch_bounds__(NTH, 2)
void fa_mma(float* __restrict__ go)
{
    extern __shared__ char smem[];
    const uint32_t sb = smem_u32(smem);
    const int tid = threadIdx.x;
    const int lane = tid & 31, wid = tid >> 5;
    const int bh = blockIdx.y;
    const int q0 = blockIdx.x * BQ;
    const int m0 = wid * 16;

    const size_t row_bytes = 128;
    const char* gqh = (const char*)g_qh + ((size_t)bh * TDIM + q0) * row_bytes;
    const char* gql = (const char*)g_ql + ((size_t)bh * TDIM + q0) * row_bytes;
    const char* gkh0 = (const char*)g_kh + (size_t)bh * TDIM * row_bytes;
    const char* gkl0 = (const char*)g_kl + (size_t)bh * TDIM * row_bytes;
    const char* gvh0 = (const char*)g_vh + (size_t)bh * TDIM * row_bytes;
    float* ob = go + (size_t)bh * TDIM * DDIM;

    // ---- K/V tile 0 into stage 0 (6 cp16/thread: KH, KL, VH) ----
    #pragma unroll
    for (int j = 0; j < 2; ++j) {
        uint32_t byte = (tid + j * NTH) * 16;
        uint32_t sw = swz(byte);
        uint32_t base = sb + KV_OFF;
        cp16(base + sw,         gkh0 + byte);
        cp16(base + 8192 + sw,  gkl0 + byte);
        cp16(base + 16384 + sw, gvh0 + byte);
    }
    CP_COMMIT();

    const int g  = lane >> 2;
    const int tq = lane & 3;
    const int r0loc = m0 + g;

    // ---- Q fragments straight from global (A-frag = 2 consecutive fp16) ----
    uint32_t aQh[4][4], aQl[4][4];
    #pragma unroll
    for (int ks = 0; ks < 4; ++ks) {
        uint32_t cb = ks * 32 + tq * 4;
        const char* r0h = gqh + (size_t)r0loc * 128;
        const char* r1h = gqh + (size_t)(r0loc + 8) * 128;
        const char* r0l = gql + (size_t)r0loc * 128;
        const char* r1l = gql + (size_t)(r0loc + 8) * 128;
        aQh[ks][0] = *(const uint32_t*)(r0h + cb);
        aQh[ks][1] = *(const uint32_t*)(r1h + cb);
        aQh[ks][2] = *(const uint32_t*)(r0h + cb + 16);
        aQh[ks][3] = *(const uint32_t*)(r1h + cb + 16);
        aQl[ks][0] = *(const uint32_t*)(r0l + cb);
        aQl[ks][1] = *(const uint32_t*)(r1l + cb);
        aQl[ks][2] = *(const uint32_t*)(r0l + cb + 16);
        aQl[ks][3] = *(const uint32_t*)(r1l + cb + 16);
    }

    // fragment address pieces (B operands via ldmatrix)
    const uint32_t arow  = m0 + ((lane >> 3) & 1) * 8 + (lane & 7);
    const uint32_t acol0 = (lane >> 4) * 16;
    const uint32_t brow  = ((lane >> 4) & 1) * 8 + (lane & 7);
    const uint32_t bcol0 = ((lane >> 3) & 1) * 16;
    const uint32_t trow0 = ((lane >> 3) & 1) * 8 + (lane & 7);
    const uint32_t tcol0 = ((lane >> 4) & 1) * 16;

    float oreg[8][4];
    #pragma unroll
    for (int i = 0; i < 8; ++i)
        #pragma unroll
        for (int j = 0; j < 4; ++j) oreg[i][j] = 0.f;
    float lsum0 = 0.f, lsum1 = 0.f;

    CP_WAIT(0);
    __syncthreads();

    for (int kt = 0; kt < KTILES; ++kt) {
        // ---- prefetch next tile into alternate stage ----
        if (kt + 1 < KTILES) {
            const size_t toff = (size_t)(kt + 1) * BK * row_bytes;
            uint32_t base = sb + KV_OFF + ((kt + 1) & 1) * KV_STAGE;
            #pragma unroll
            for (int j = 0; j < 2; ++j) {
                uint32_t byte = (tid + j * NTH) * 16;
                uint32_t sw = swz(byte);
                cp16(base + sw,         gkh0 + toff + byte);
                cp16(base + 8192 + sw,  gkl0 + toff + byte);
                cp16(base + 16384 + sw, gvh0 + toff + byte);
            }
            CP_COMMIT();
        }

        // early mask fetch
        unsigned long long mw0 =
            *(const unsigned long long*)(g_maskbits + (size_t)(q0 + r0loc) * (TDIM / 32) + kt * 2);
        unsigned long long mw1 =
            *(const unsigned long long*)(g_maskbits + (size_t)(q0 + r0loc + 8) * (TDIM / 32) + kt * 2);

        const uint32_t kvb = sb + KV_OFF + (kt & 1) * KV_STAGE;
        const uint32_t khb = kvb, klb = kvb + 8192, vhb = kvb + 16384;

        // ---- S = Q K^T (3-term fp16 emulation) ----
        float s[8][4];
        #pragma unroll
        for (int i = 0; i < 8; ++i)
            #pragma unroll
            for (int j = 0; j < 4; ++j) s[i][j] = 0.f;

        #pragma unroll
        for (int ks = 0; ks < 4; ++ks) {
            #pragma unroll
            for (int np = 0; np < 4; ++np) {
                uint32_t sw = swz((np * 16 + brow) * 128 + ks * 32 + bcol0);
                uint32_t bHf[4], bLf[4];
                ldsm_x4(bHf, khb + sw);
                ldsm_x4(bLf, klb + sw);
                mma16816(s[2 * np],     aQh[ks], bHf[0], bHf[1]);
                mma16816(s[2 * np + 1], aQh[ks], bHf[2], bHf[3]);
                mma16816(s[2 * np],     aQh[ks], bLf[0], bLf[1]);
                mma16816(s[2 * np + 1], aQh[ks], bLf[2], bLf[3]);
                mma16816(s[2 * np],     aQl[ks], bHf[0], bHf[1]);
                mma16816(s[2 * np + 1], aQl[ks], bHf[2], bHf[3]);
            }
        }

        // ---- mask + exp2 + write P as fp16 (warp-private rows) ----
        #pragma unroll
        for (int ng = 0; ng < 8; ++ng) {
            int c = ng * 8 + tq * 2;
            float p0 = ((mw0 >> c) & 1ULL)       ? 0.f : ex2f(s[ng][0]);
            float p1 = ((mw0 >> (c + 1)) & 1ULL) ? 0.f : ex2f(s[ng][1]);
            float p2 = ((mw1 >> c) & 1ULL)       ? 0.f : ex2f(s[ng][2]);
            float p3 = ((mw1 >> (c + 1)) & 1ULL) ? 0.f : ex2f(s[ng][3]);
            lsum0 += p0 + p1;
            lsum1 += p2 + p3;
            *(uint32_t*)(smem + PH_OFF + swz((uint32_t)(r0loc * 128 + c * 2))) = pack_h2(p0, p1);
            *(uint32_t*)(smem + PH_OFF + swz((uint32_t)((r0loc + 8) * 128 + c * 2))) = pack_h2(p2, p3);
        }
        __syncwarp();

        // ---- O += P V (single-term fp16), V via ldmatrix.trans ----
        #pragma unroll
        for (int ks = 0; ks < 4; ++ks) {
            uint32_t swA = swz(arow * 128 + ks * 32 + acol0);
            uint32_t aP[4];
            ldsm_x4(aP, sb + PH_OFF + swA);
            #pragma unroll
            for (int np = 0; np < 4; ++np) {
                uint32_t swB = swz((ks * 16 + trow0) * 128 + np * 32 + tcol0);
                uint32_t bVf[4];
                ldsm_x4_t(bVf, vhb + swB);
                mma16816(oreg[2 * np],     aP, bVf[0], bVf[1]);
                mma16816(oreg[2 * np + 1], aP, bVf[2], bVf[3]);
            }
        }

        // next tile resident + everyone done with this stage
        if (kt + 1 < KTILES) CP_WAIT(0);
        __syncthreads();
    }

    // ---- epilogue ----
    #pragma unroll
    for (int off = 1; off <= 2; off <<= 1) {
        lsum0 += __shfl_xor_sync(0xffffffffu, lsum0, off);
        lsum1 += __shfl_xor_sync(0xffffffffu, lsum1, off);
    }
    float inv0 = 1.f / lsum0;
    float inv1 = 1.f / lsum1;

    float* orow0 = ob + (size_t)(q0 + r0loc) * DDIM;
    float* orow1 = ob + (size_t)(q0 + r0loc + 8) * DDIM;
    #pragma unroll
    for (int ng = 0; ng < 8; ++ng) {
        int c = ng * 8 + tq * 2;
        *(float2*)(orow0 + c) = make_float2(oreg[ng][0] * inv0, oreg[ng][1] * inv0);
        *(float2*)(orow1 + c) = make_float2(oreg[ng][2] * inv1, oreg[ng][3] * inv1);
    }
}

extern "C" void kernel_launch(void* const* d_in, const int* in_sizes, int n_in,
                              void* d_out, int out_size) {
    const float* q = (const float*)d_in[0];
    const float* k = (const float*)d_in[1];
    const float* v = (const float*)d_in[2];
    const int* mask = (const int*)d_in[3];
    float* out = (float*)d_out;

    uint4 *qh, *ql, *kh, *kl, *vh;
    cudaGetSymbolAddress((void**)&qh, g_qh);
    cudaGetSymbolAddress((void**)&ql, g_ql);
    cudaGetSymbolAddress((void**)&kh, g_kh);
    cudaGetSymbolAddress((void**)&kl, g_kl);
    cudaGetSymbolAddress((void**)&vh, g_vh);

    pack_mask<<<(TDIM * TDIM / 32 + 255) / 256, 256>>>(mask);

    const int n16 = (int)(NELEM / 8);
    // Q scale folds softmax 1/sqrt(D) and log2(e): exp(s) == exp2(s*log2e)
    const float qscale = 0.125f * 1.44269504088896340736f;
    cvt_split_f16<<<(n16 + 255) / 256, 256>>>((const float4*)q, qh, ql, qscale, n16);
    cvt_split_f16<<<(n16 + 255) / 256, 256>>>((const float4*)k, kh, kl, 1.0f, n16);
    cvt_f16<<<(n16 + 255) / 256, 256>>>((const float4*)v, vh, n16);

    cudaFuncSetAttribute(fa_mma, cudaFuncAttributeMaxDynamicSharedMemorySize, SMEM_BYTES);
    dim3 grid(TDIM / BQ, BH);
    fa_mma<<<grid, NTH, SMEM_BYTES>>>(out);
}

// round 11
// speedup vs baseline: 2.2642x; 1.3743x over previous
#include <cuda_runtime.h>
#include <cuda_fp16.h>
#include <cstdint>

#define TDIM 2048
#define DDIM 64
#define BH 32
#define BQ 128
#define BK 64
#define NTH 256
#define KTILES (TDIM / BK)

// smem layout (bytes): P fp16 [128][128B], KV double-buffered stages {KH,VH} 8KB each
#define PH_OFF 0
#define KV_OFF 16384
#define KV_STAGE 16384
#define SMEM_BYTES (KV_OFF + 2 * KV_STAGE)   // 48 KB -> 2 CTAs/SM

#define NELEM ((size_t)BH * TDIM * DDIM)

__device__ unsigned int g_maskbits[(size_t)TDIM * TDIM / 32];  // 512 KB
__device__ uint4 g_qh[NELEM / 8];
__device__ uint4 g_kh[NELEM / 8];
__device__ uint4 g_vh[NELEM / 8];

// ---------------- helpers ----------------
__device__ __forceinline__ uint32_t smem_u32(const void* p) {
    uint32_t a;
    asm("{ .reg .u64 t; cvta.to.shared.u64 t, %1; cvt.u32.u64 %0, t; }" : "=r"(a) : "l"(p));
    return a;
}
__device__ __forceinline__ uint32_t swz(uint32_t byte) {
    return byte ^ ((byte >> 3) & 0x70);
}
__device__ __forceinline__ void cp16(uint32_t dst, const void* src) {
    asm volatile("cp.async.cg.shared.global [%0], [%1], 16;" :: "r"(dst), "l"(src));
}
#define CP_COMMIT() asm volatile("cp.async.commit_group;" ::: "memory")
#define CP_WAIT(n)  asm volatile("cp.async.wait_group %0;" :: "n"(n) : "memory")

__device__ __forceinline__ void ldsm_x4(uint32_t (&r)[4], uint32_t addr) {
    asm volatile("ldmatrix.sync.aligned.m8n8.x4.shared.b16 {%0,%1,%2,%3}, [%4];"
                 : "=r"(r[0]), "=r"(r[1]), "=r"(r[2]), "=r"(r[3]) : "r"(addr));
}
__device__ __forceinline__ void ldsm_x4_t(uint32_t (&r)[4], uint32_t addr) {
    asm volatile("ldmatrix.sync.aligned.m8n8.x4.trans.shared.b16 {%0,%1,%2,%3}, [%4];"
                 : "=r"(r[0]), "=r"(r[1]), "=r"(r[2]), "=r"(r[3]) : "r"(addr));
}
// fp16 MMA, fp32 accumulate
__device__ __forceinline__ void mma16816(float (&c)[4], const uint32_t (&a)[4],
                                         uint32_t b0, uint32_t b1) {
    asm volatile(
        "mma.sync.aligned.m16n8k16.row.col.f32.f16.f16.f32 "
        "{%0,%1,%2,%3}, {%4,%5,%6,%7}, {%8,%9}, {%0,%1,%2,%3};"
        : "+f"(c[0]), "+f"(c[1]), "+f"(c[2]), "+f"(c[3])
        : "r"(a[0]), "r"(a[1]), "r"(a[2]), "r"(a[3]), "r"(b0), "r"(b1));
}
__device__ __forceinline__ float ex2f(float x) {
    float r;
    asm("ex2.approx.f32 %0, %1;" : "=f"(r) : "f"(x));
    return r;
}
__device__ __forceinline__ uint32_t pack_h2(float x, float y) {
    __half hx = __float2half_rn(x), hy = __float2half_rn(y);
    return ((uint32_t)__half_as_ushort(hy) << 16) | __half_as_ushort(hx);
}

// ---------------- prepass kernels ----------------
__global__ void pack_mask(const int* __restrict__ m) {
    int w = blockIdx.x * blockDim.x + threadIdx.x;
    if (w >= (TDIM * TDIM) / 32) return;
    const int4* p = (const int4*)(m + (size_t)w * 32);
    unsigned int bits = 0;
    #pragma unroll
    for (int i = 0; i < 8; ++i) {
        int4 v = p[i];
        bits |= (unsigned)(v.x != 0) << (i * 4);
        bits |= (unsigned)(v.y != 0) << (i * 4 + 1);
        bits |= (unsigned)(v.z != 0) << (i * 4 + 2);
        bits |= (unsigned)(v.w != 0) << (i * 4 + 3);
    }
    g_maskbits[w] = bits;
}

// fp32 -> fp16 (8 elems/thread), with scale
__global__ void cvt_f16(const float4* __restrict__ src, uint4* __restrict__ dst,
                        float scale, int n16) {
    int i = blockIdx.x * blockDim.x + threadIdx.x;
    if (i >= n16) return;
    float4 a = src[2 * i], b = src[2 * i + 1];
    uint4 w;
    w.x = pack_h2(a.x * scale, a.y * scale);
    w.y = pack_h2(a.z * scale, a.w * scale);
    w.z = pack_h2(b.x * scale, b.y * scale);
    w.w = pack_h2(b.z * scale, b.w * scale);
    dst[i] = w;
}

// -------- main kernel: 8 warps, warp-private P, 2 CTAs/SM, single-term fp16 --------
__global__ __launch_bounds__(NTH, 2)
void fa_mma(float* __restrict__ go)
{
    extern __shared__ char smem[];
    const uint32_t sb = smem_u32(smem);
    const int tid = threadIdx.x;
    const int lane = tid & 31, wid = tid >> 5;
    const int bh = blockIdx.y;
    const int q0 = blockIdx.x * BQ;
    const int m0 = wid * 16;

    const size_t row_bytes = 128;
    const char* gqh = (const char*)g_qh + ((size_t)bh * TDIM + q0) * row_bytes;
    const char* gkh0 = (const char*)g_kh + (size_t)bh * TDIM * row_bytes;
    const char* gvh0 = (const char*)g_vh + (size_t)bh * TDIM * row_bytes;
    float* ob = go + (size_t)bh * TDIM * DDIM;

    // ---- K/V tile 0 into stage 0 (4 cp16/thread: KH, VH) ----
    #pragma unroll
    for (int j = 0; j < 2; ++j) {
        uint32_t byte = (tid + j * NTH) * 16;
        uint32_t sw = swz(byte);
        uint32_t base = sb + KV_OFF;
        cp16(base + sw,        gkh0 + byte);
        cp16(base + 8192 + sw, gvh0 + byte);
    }
    CP_COMMIT();

    const int g  = lane >> 2;
    const int tq = lane & 3;
    const int r0loc = m0 + g;

    // ---- Q fragments straight from global (A-frag = 2 consecutive fp16) ----
    uint32_t aQ[4][4];
    #pragma unroll
    for (int ks = 0; ks < 4; ++ks) {
        uint32_t cb = ks * 32 + tq * 4;
        const char* r0h = gqh + (size_t)r0loc * 128;
        const char* r1h = gqh + (size_t)(r0loc + 8) * 128;
        aQ[ks][0] = *(const uint32_t*)(r0h + cb);
        aQ[ks][1] = *(const uint32_t*)(r1h + cb);
        aQ[ks][2] = *(const uint32_t*)(r0h + cb + 16);
        aQ[ks][3] = *(const uint32_t*)(r1h + cb + 16);
    }

    // fragment address pieces (B operands via ldmatrix)
    const uint32_t arow  = m0 + ((lane >> 3) & 1) * 8 + (lane & 7);
    const uint32_t acol0 = (lane >> 4) * 16;
    const uint32_t brow  = ((lane >> 4) & 1) * 8 + (lane & 7);
    const uint32_t bcol0 = ((lane >> 3) & 1) * 16;
    const uint32_t trow0 = ((lane >> 3) & 1) * 8 + (lane & 7);
    const uint32_t tcol0 = ((lane >> 4) & 1) * 16;

    float oreg[8][4];
    #pragma unroll
    for (int i = 0; i < 8; ++i)
        #pragma unroll
        for (int j = 0; j < 4; ++j) oreg[i][j] = 0.f;
    float lsum0 = 0.f, lsum1 = 0.f;

    CP_WAIT(0);
    __syncthreads();

    for (int kt = 0; kt < KTILES; ++kt) {
        // ---- prefetch next tile into alternate stage ----
        if (kt + 1 < KTILES) {
            const size_t toff = (size_t)(kt + 1) * BK * row_bytes;
            uint32_t base = sb + KV_OFF + ((kt + 1) & 1) * KV_STAGE;
            #pragma unroll
            for (int j = 0; j < 2; ++j) {
                uint32_t byte = (tid + j * NTH) * 16;
                uint32_t sw = swz(byte);
                cp16(base + sw,        gkh0 + toff + byte);
                cp16(base + 8192 + sw, gvh0 + toff + byte);
            }
            CP_COMMIT();
        }

        // early mask fetch
        unsigned long long mw0 =
            *(const unsigned long long*)(g_maskbits + (size_t)(q0 + r0loc) * (TDIM / 32) + kt * 2);
        unsigned long long mw1 =
            *(const unsigned long long*)(g_maskbits + (size_t)(q0 + r0loc + 8) * (TDIM / 32) + kt * 2);

        const uint32_t kvb = sb + KV_OFF + (kt & 1) * KV_STAGE;
        const uint32_t khb = kvb, vhb = kvb + 8192;

        // ---- S = Q K^T (single-term fp16) ----
        float s[8][4];
        #pragma unroll
        for (int i = 0; i < 8; ++i)
            #pragma unroll
            for (int j = 0; j < 4; ++j) s[i][j] = 0.f;

        #pragma unroll
        for (int ks = 0; ks < 4; ++ks) {
            #pragma unroll
            for (int np = 0; np < 4; ++np) {
                uint32_t sw = swz((np * 16 + brow) * 128 + ks * 32 + bcol0);
                uint32_t bHf[4];
                ldsm_x4(bHf, khb + sw);
                mma16816(s[2 * np],     aQ[ks], bHf[0], bHf[1]);
                mma16816(s[2 * np + 1], aQ[ks], bHf[2], bHf[3]);
            }
        }

        // ---- mask + exp2 + write P as fp16 (warp-private rows) ----
        #pragma unroll
        for (int ng = 0; ng < 8; ++ng) {
            int c = ng * 8 + tq * 2;
            float p0 = ((mw0 >> c) & 1ULL)       ? 0.f : ex2f(s[ng][0]);
            float p1 = ((mw0 >> (c + 1)) & 1ULL) ? 0.f : ex2f(s[ng][1]);
            float p2 = ((mw1 >> c) & 1ULL)       ? 0.f : ex2f(s[ng][2]);
            float p3 = ((mw1 >> (c + 1)) & 1ULL) ? 0.f : ex2f(s[ng][3]);
            lsum0 += p0 + p1;
            lsum1 += p2 + p3;
            *(uint32_t*)(smem + PH_OFF + swz((uint32_t)(r0loc * 128 + c * 2))) = pack_h2(p0, p1);
            *(uint32_t*)(smem + PH_OFF + swz((uint32_t)((r0loc + 8) * 128 + c * 2))) = pack_h2(p2, p3);
        }
        __syncwarp();

        // ---- O += P V (single-term fp16), V via ldmatrix.trans ----
        #pragma unroll
        for (int ks = 0; ks < 4; ++ks) {
            uint32_t swA = swz(arow * 128 + ks * 32 + acol0);
            uint32_t aP[4];
            ldsm_x4(aP, sb + PH_OFF + swA);
            #pragma unroll
            for (int np = 0; np < 4; ++np) {
                uint32_t swB = swz((ks * 16 + trow0) * 128 + np * 32 + tcol0);
                uint32_t bVf[4];
                ldsm_x4_t(bVf, vhb + swB);
                mma16816(oreg[2 * np],     aP, bVf[0], bVf[1]);
                mma16816(oreg[2 * np + 1], aP, bVf[2], bVf[3]);
            }
        }

        // next tile resident + everyone done with this stage
        if (kt + 1 < KTILES) CP_WAIT(0);
        __syncthreads();
    }

    // ---- epilogue ----
    #pragma unroll
    for (int off = 1; off <= 2; off <<= 1) {
        lsum0 += __shfl_xor_sync(0xffffffffu, lsum0, off);
        lsum1 += __shfl_xor_sync(0xffffffffu, lsum1, off);
    }
    float inv0 = 1.f / lsum0;
    float inv1 = 1.f / lsum1;

    float* orow0 = ob + (size_t)(q0 + r0loc) * DDIM;
    float* orow1 = ob + (size_t)(q0 + r0loc + 8) * DDIM;
    #pragma unroll
    for (int ng = 0; ng < 8; ++ng) {
        int c = ng * 8 + tq * 2;
        *(float2*)(orow0 + c) = make_float2(oreg[ng][0] * inv0, oreg[ng][1] * inv0);
        *(float2*)(orow1 + c) = make_float2(oreg[ng][2] * inv1, oreg[ng][3] * inv1);
    }
}

extern "C" void kernel_launch(void* const* d_in, const int* in_sizes, int n_in,
                              void* d_out, int out_size) {
    const float* q = (const float*)d_in[0];
    const float* k = (const float*)d_in[1];
    const float* v = (const float*)d_in[2];
    const int* mask = (const int*)d_in[3];
    float* out = (float*)d_out;

    uint4 *qh, *kh, *vh;
    cudaGetSymbolAddress((void**)&qh, g_qh);
    cudaGetSymbolAddress((void**)&kh, g_kh);
    cudaGetSymbolAddress((void**)&vh, g_vh);

    pack_mask<<<(TDIM * TDIM / 32 + 255) / 256, 256>>>(mask);

    const int n16 = (int)(NELEM / 8);
    // Q scale folds softmax 1/sqrt(D) and log2(e): exp(s) == exp2(s*log2e)
    const float qscale = 0.125f * 1.44269504088896340736f;
    cvt_f16<<<(n16 + 255) / 256, 256>>>((const float4*)q, qh, qscale, n16);
    cvt_f16<<<(n16 + 255) / 256, 256>>>((const float4*)k, kh, 1.0f, n16);
    cvt_f16<<<(n16 + 255) / 256, 256>>>((const float4*)v, vh, 1.0f, n16);

    cudaFuncSetAttribute(fa_mma, cudaFuncAttributeMaxDynamicSharedMemorySize, SMEM_BYTES);
    dim3 grid(TDIM / BQ, BH);
    fa_mma<<<grid, NTH, SMEM_BYTES>>>(out);
}

// round 12
// speedup vs baseline: 2.6055x; 1.1508x over previous
#include <cuda_runtime.h>
#include <cuda_fp16.h>
#include <cstdint>

#define TDIM 2048
#define DDIM 64
#define BH 32
#define BQ 128
#define BK 64
#define NTH 256
#define KTILES (TDIM / BK)

// smem layout (bytes): KV double-buffered stages {KH,VH} 8KB each — no P buffer
#define KV_STAGE 16384
#define SMEM_BYTES (2 * KV_STAGE)   // 32 KB -> 2 CTAs/SM easily

#define NELEM ((size_t)BH * TDIM * DDIM)

__device__ unsigned int g_maskbits[(size_t)TDIM * TDIM / 32];  // 512 KB
__device__ uint4 g_qh[NELEM / 8];
__device__ uint4 g_kh[NELEM / 8];
__device__ uint4 g_vh[NELEM / 8];

// ---------------- helpers ----------------
__device__ __forceinline__ uint32_t smem_u32(const void* p) {
    uint32_t a;
    asm("{ .reg .u64 t; cvta.to.shared.u64 t, %1; cvt.u32.u64 %0, t; }" : "=r"(a) : "l"(p));
    return a;
}
__device__ __forceinline__ uint32_t swz(uint32_t byte) {
    return byte ^ ((byte >> 3) & 0x70);
}
__device__ __forceinline__ void cp16(uint32_t dst, const void* src) {
    asm volatile("cp.async.cg.shared.global [%0], [%1], 16;" :: "r"(dst), "l"(src));
}
#define CP_COMMIT() asm volatile("cp.async.commit_group;" ::: "memory")
#define CP_WAIT(n)  asm volatile("cp.async.wait_group %0;" :: "n"(n) : "memory")

__device__ __forceinline__ void ldsm_x4(uint32_t (&r)[4], uint32_t addr) {
    asm volatile("ldmatrix.sync.aligned.m8n8.x4.shared.b16 {%0,%1,%2,%3}, [%4];"
                 : "=r"(r[0]), "=r"(r[1]), "=r"(r[2]), "=r"(r[3]) : "r"(addr));
}
__device__ __forceinline__ void ldsm_x4_t(uint32_t (&r)[4], uint32_t addr) {
    asm volatile("ldmatrix.sync.aligned.m8n8.x4.trans.shared.b16 {%0,%1,%2,%3}, [%4];"
                 : "=r"(r[0]), "=r"(r[1]), "=r"(r[2]), "=r"(r[3]) : "r"(addr));
}
// fp16 MMA, fp32 accumulate
__device__ __forceinline__ void mma16816(float (&c)[4], const uint32_t (&a)[4],
                                         uint32_t b0, uint32_t b1) {
    asm volatile(
        "mma.sync.aligned.m16n8k16.row.col.f32.f16.f16.f32 "
        "{%0,%1,%2,%3}, {%4,%5,%6,%7}, {%8,%9}, {%0,%1,%2,%3};"
        : "+f"(c[0]), "+f"(c[1]), "+f"(c[2]), "+f"(c[3])
        : "r"(a[0]), "r"(a[1]), "r"(a[2]), "r"(a[3]), "r"(b0), "r"(b1));
}
__device__ __forceinline__ float ex2f(float x) {
    float r;
    asm("ex2.approx.f32 %0, %1;" : "=f"(r) : "f"(x));
    return r;
}
// pack two fp32 into fp16x2 (lo=x, hi=y) — single CVT
__device__ __forceinline__ uint32_t pack_h2(float x, float y) {
    uint32_t r;
    asm("cvt.rn.f16x2.f32 %0, %1, %2;" : "=r"(r) : "f"(y), "f"(x));
    return r;
}

// ---------------- prepass kernels ----------------
__global__ void pack_mask(const int* __restrict__ m) {
    int w = blockIdx.x * blockDim.x + threadIdx.x;
    if (w >= (TDIM * TDIM) / 32) return;
    const int4* p = (const int4*)(m + (size_t)w * 32);
    unsigned int bits = 0;
    #pragma unroll
    for (int i = 0; i < 8; ++i) {
        int4 v = p[i];
        bits |= (unsigned)(v.x != 0) << (i * 4);
        bits |= (unsigned)(v.y != 0) << (i * 4 + 1);
        bits |= (unsigned)(v.z != 0) << (i * 4 + 2);
        bits |= (unsigned)(v.w != 0) << (i * 4 + 3);
    }
    g_maskbits[w] = bits;
}

// fp32 -> fp16 (8 elems/thread), with scale
__global__ void cvt_f16(const float4* __restrict__ src, uint4* __restrict__ dst,
                        float scale, int n16) {
    int i = blockIdx.x * blockDim.x + threadIdx.x;
    if (i >= n16) return;
    float4 a = src[2 * i], b = src[2 * i + 1];
    uint4 w;
    w.x = pack_h2(a.x * scale, a.y * scale);
    w.y = pack_h2(a.z * scale, a.w * scale);
    w.z = pack_h2(b.x * scale, b.y * scale);
    w.w = pack_h2(b.z * scale, b.w * scale);
    dst[i] = w;
}

// -------- main kernel: 8 warps, register-resident P, 2 CTAs/SM --------
__global__ __launch_bounds__(NTH, 2)
void fa_mma(float* __restrict__ go)
{
    extern __shared__ char smem[];
    const uint32_t sb = smem_u32(smem);
    const int tid = threadIdx.x;
    const int lane = tid & 31, wid = tid >> 5;
    const int bh = blockIdx.y;
    const int q0 = blockIdx.x * BQ;
    const int m0 = wid * 16;

    const size_t row_bytes = 128;
    const char* gqh = (const char*)g_qh + ((size_t)bh * TDIM + q0) * row_bytes;
    const char* gkh0 = (const char*)g_kh + (size_t)bh * TDIM * row_bytes;
    const char* gvh0 = (const char*)g_vh + (size_t)bh * TDIM * row_bytes;
    float* ob = go + (size_t)bh * TDIM * DDIM;

    // ---- K/V tile 0 into stage 0 (4 cp16/thread: KH, VH) ----
    #pragma unroll
    for (int j = 0; j < 2; ++j) {
        uint32_t byte = (tid + j * NTH) * 16;
        uint32_t sw = swz(byte);
        cp16(sb + sw,        gkh0 + byte);
        cp16(sb + 8192 + sw, gvh0 + byte);
    }
    CP_COMMIT();

    const int g  = lane >> 2;
    const int tq = lane & 3;
    const int r0loc = m0 + g;

    // ---- Q fragments straight from global (A-frag = 2 consecutive fp16) ----
    uint32_t aQ[4][4];
    #pragma unroll
    for (int ks = 0; ks < 4; ++ks) {
        uint32_t cb = ks * 32 + tq * 4;
        const char* r0h = gqh + (size_t)r0loc * 128;
        const char* r1h = gqh + (size_t)(r0loc + 8) * 128;
        aQ[ks][0] = *(const uint32_t*)(r0h + cb);
        aQ[ks][1] = *(const uint32_t*)(r1h + cb);
        aQ[ks][2] = *(const uint32_t*)(r0h + cb + 16);
        aQ[ks][3] = *(const uint32_t*)(r1h + cb + 16);
    }

    // fragment address pieces (B operands via ldmatrix)
    const uint32_t brow  = ((lane >> 4) & 1) * 8 + (lane & 7);
    const uint32_t bcol0 = ((lane >> 3) & 1) * 16;
    const uint32_t trow0 = ((lane >> 3) & 1) * 8 + (lane & 7);
    const uint32_t tcol0 = ((lane >> 4) & 1) * 16;

    float oreg[8][4];
    #pragma unroll
    for (int i = 0; i < 8; ++i)
        #pragma unroll
        for (int j = 0; j < 4; ++j) oreg[i][j] = 0.f;
    float lsum0 = 0.f, lsum1 = 0.f;

    CP_WAIT(0);
    __syncthreads();

    for (int kt = 0; kt < KTILES; ++kt) {
        // ---- prefetch next tile into alternate stage ----
        if (kt + 1 < KTILES) {
            const size_t toff = (size_t)(kt + 1) * BK * row_bytes;
            uint32_t base = sb + ((kt + 1) & 1) * KV_STAGE;
            #pragma unroll
            for (int j = 0; j < 2; ++j) {
                uint32_t byte = (tid + j * NTH) * 16;
                uint32_t sw = swz(byte);
                cp16(base + sw,        gkh0 + toff + byte);
                cp16(base + 8192 + sw, gvh0 + toff + byte);
            }
            CP_COMMIT();
        }

        // early mask fetch
        unsigned long long mw0 =
            *(const unsigned long long*)(g_maskbits + (size_t)(q0 + r0loc) * (TDIM / 32) + kt * 2);
        unsigned long long mw1 =
            *(const unsigned long long*)(g_maskbits + (size_t)(q0 + r0loc + 8) * (TDIM / 32) + kt * 2);

        const uint32_t kvb = sb + (kt & 1) * KV_STAGE;
        const uint32_t khb = kvb, vhb = kvb + 8192;

        // ---- S = Q K^T (single-term fp16) ----
        float s[8][4];
        #pragma unroll
        for (int i = 0; i < 8; ++i)
            #pragma unroll
            for (int j = 0; j < 4; ++j) s[i][j] = 0.f;

        #pragma unroll
        for (int ks = 0; ks < 4; ++ks) {
            #pragma unroll
            for (int np = 0; np < 4; ++np) {
                uint32_t sw = swz((np * 16 + brow) * 128 + ks * 32 + bcol0);
                uint32_t bHf[4];
                ldsm_x4(bHf, khb + sw);
                mma16816(s[2 * np],     aQ[ks], bHf[0], bHf[1]);
                mma16816(s[2 * np + 1], aQ[ks], bHf[2], bHf[3]);
            }
        }

        // ---- mask + exp2 -> register-resident P (A-frag layout, no smem) ----
        // C-frag (row g/g+8, cols 8*ng + 2tq,2tq+1) maps exactly onto the
        // m16n8k16 A-frag for PV: aP[ks] = {p[2ks][0,1], p[2ks][2,3],
        //                                   p[2ks+1][0,1], p[2ks+1][2,3]}
        uint32_t aP[4][4];
        #pragma unroll
        for (int ks = 0; ks < 4; ++ks) {
            #pragma unroll
            for (int h = 0; h < 2; ++h) {          // n8-tile 2ks+h
                int ng = 2 * ks + h;
                int c = ng * 8 + tq * 2;
                float p0 = ((mw0 >> c) & 1ULL)       ? 0.f : ex2f(s[ng][0]);
                float p1 = ((mw0 >> (c + 1)) & 1ULL) ? 0.f : ex2f(s[ng][1]);
                float p2 = ((mw1 >> c) & 1ULL)       ? 0.f : ex2f(s[ng][2]);
                float p3 = ((mw1 >> (c + 1)) & 1ULL) ? 0.f : ex2f(s[ng][3]);
                lsum0 += p0 + p1;
                lsum1 += p2 + p3;
                aP[ks][2 * h]     = pack_h2(p0, p1);   // row g
                aP[ks][2 * h + 1] = pack_h2(p2, p3);   // row g+8
            }
        }

        // ---- O += P V (single-term fp16), V via ldmatrix.trans ----
        #pragma unroll
        for (int ks = 0; ks < 4; ++ks) {
            #pragma unroll
            for (int np = 0; np < 4; ++np) {
                uint32_t swB = swz((ks * 16 + trow0) * 128 + np * 32 + tcol0);
                uint32_t bVf[4];
                ldsm_x4_t(bVf, vhb + swB);
                mma16816(oreg[2 * np],     aP[ks], bVf[0], bVf[1]);
                mma16816(oreg[2 * np + 1], aP[ks], bVf[2], bVf[3]);
            }
        }

        // next tile resident + everyone done with this stage
        if (kt + 1 < KTILES) CP_WAIT(0);
        __syncthreads();
    }

    // ---- epilogue ----
    #pragma unroll
    for (int off = 1; off <= 2; off <<= 1) {
        lsum0 += __shfl_xor_sync(0xffffffffu, lsum0, off);
        lsum1 += __shfl_xor_sync(0xffffffffu, lsum1, off);
    }
    float inv0 = 1.f / lsum0;
    float inv1 = 1.f / lsum1;

    float* orow0 = ob + (size_t)(q0 + r0loc) * DDIM;
    float* orow1 = ob + (size_t)(q0 + r0loc + 8) * DDIM;
    #pragma unroll
    for (int ng = 0; ng < 8; ++ng) {
        int c = ng * 8 + tq * 2;
        *(float2*)(orow0 + c) = make_float2(oreg[ng][0] * inv0, oreg[ng][1] * inv0);
        *(float2*)(orow1 + c) = make_float2(oreg[ng][2] * inv1, oreg[ng][3] * inv1);
    }
}

extern "C" void kernel_launch(void* const* d_in, const int* in_sizes, int n_in,
                              void* d_out, int out_size) {
    const float* q = (const float*)d_in[0];
    const float* k = (const float*)d_in[1];
    const float* v = (const float*)d_in[2];
    const int* mask = (const int*)d_in[3];
    float* out = (float*)d_out;

    uint4 *qh, *kh, *vh;
    cudaGetSymbolAddress((void**)&qh, g_qh);
    cudaGetSymbolAddress((void**)&kh, g_kh);
    cudaGetSymbolAddress((void**)&vh, g_vh);

    pack_mask<<<(TDIM * TDIM / 32 + 255) / 256, 256>>>(mask);

    const int n16 = (int)(NELEM / 8);
    // Q scale folds softmax 1/sqrt(D) and log2(e): exp(s) == exp2(s*log2e)
    const float qscale = 0.125f * 1.44269504088896340736f;
    cvt_f16<<<(n16 + 255) / 256, 256>>>((const float4*)q, qh, qscale, n16);
    cvt_f16<<<(n16 + 255) / 256, 256>>>((const float4*)k, kh, 1.0f, n16);
    cvt_f16<<<(n16 + 255) / 256, 256>>>((const float4*)v, vh, 1.0f, n16);

    cudaFuncSetAttribute(fa_mma, cudaFuncAttributeMaxDynamicSharedMemorySize, SMEM_BYTES);
    dim3 grid(TDIM / BQ, BH);
    fa_mma<<<grid, NTH, SMEM_BYTES>>>(out);
}

// round 13
// speedup vs baseline: 2.6949x; 1.0343x over previous
#include <cuda_runtime.h>
#include <cuda_fp16.h>
#include <cstdint>

#define TDIM 2048
#define DDIM 64
#define BH 32
#define BQ 64
#define BK 64
#define NTH 128
#define KTILES (TDIM / BK)

// smem layout (bytes): KV double-buffered stages {KH,VH} 8KB each
#define KV_STAGE 16384
#define SMEM_BYTES (2 * KV_STAGE)   // 32 KB -> 4 CTAs/SM

#define NELEM ((size_t)BH * TDIM * DDIM)

__device__ unsigned int g_maskbits[(size_t)TDIM * TDIM / 32];  // 512 KB
__device__ uint4 g_qh[NELEM / 8];
__device__ uint4 g_kh[NELEM / 8];
__device__ uint4 g_vh[NELEM / 8];

// ---------------- helpers ----------------
__device__ __forceinline__ uint32_t smem_u32(const void* p) {
    uint32_t a;
    asm("{ .reg .u64 t; cvta.to.shared.u64 t, %1; cvt.u32.u64 %0, t; }" : "=r"(a) : "l"(p));
    return a;
}
__device__ __forceinline__ uint32_t swz(uint32_t byte) {
    return byte ^ ((byte >> 3) & 0x70);
}
__device__ __forceinline__ void cp16(uint32_t dst, const void* src) {
    asm volatile("cp.async.cg.shared.global [%0], [%1], 16;" :: "r"(dst), "l"(src));
}
#define CP_COMMIT() asm volatile("cp.async.commit_group;" ::: "memory")
#define CP_WAIT(n)  asm volatile("cp.async.wait_group %0;" :: "n"(n) : "memory")

__device__ __forceinline__ void ldsm_x4(uint32_t (&r)[4], uint32_t addr) {
    asm volatile("ldmatrix.sync.aligned.m8n8.x4.shared.b16 {%0,%1,%2,%3}, [%4];"
                 : "=r"(r[0]), "=r"(r[1]), "=r"(r[2]), "=r"(r[3]) : "r"(addr));
}
__device__ __forceinline__ void ldsm_x4_t(uint32_t (&r)[4], uint32_t addr) {
    asm volatile("ldmatrix.sync.aligned.m8n8.x4.trans.shared.b16 {%0,%1,%2,%3}, [%4];"
                 : "=r"(r[0]), "=r"(r[1]), "=r"(r[2]), "=r"(r[3]) : "r"(addr));
}
// fp16 MMA, fp32 accumulate
__device__ __forceinline__ void mma16816(float (&c)[4], const uint32_t (&a)[4],
                                         uint32_t b0, uint32_t b1) {
    asm volatile(
        "mma.sync.aligned.m16n8k16.row.col.f32.f16.f16.f32 "
        "{%0,%1,%2,%3}, {%4,%5,%6,%7}, {%8,%9}, {%0,%1,%2,%3};"
        : "+f"(c[0]), "+f"(c[1]), "+f"(c[2]), "+f"(c[3])
        : "r"(a[0]), "r"(a[1]), "r"(a[2]), "r"(a[3]), "r"(b0), "r"(b1));
}
__device__ __forceinline__ float ex2f(float x) {
    float r;
    asm("ex2.approx.f32 %0, %1;" : "=f"(r) : "f"(x));
    return r;
}
// pack two fp32 into fp16x2 (lo=x, hi=y) — single CVT
__device__ __forceinline__ uint32_t pack_h2(float x, float y) {
    uint32_t r;
    asm("cvt.rn.f16x2.f32 %0, %1, %2;" : "=r"(r) : "f"(y), "f"(x));
    return r;
}

// ---------------- prepass kernels ----------------
__global__ void pack_mask(const int* __restrict__ m) {
    int w = blockIdx.x * blockDim.x + threadIdx.x;
    if (w >= (TDIM * TDIM) / 32) return;
    const int4* p = (const int4*)(m + (size_t)w * 32);
    unsigned int bits = 0;
    #pragma unroll
    for (int i = 0; i < 8; ++i) {
        int4 v = p[i];
        bits |= (unsigned)(v.x != 0) << (i * 4);
        bits |= (unsigned)(v.y != 0) << (i * 4 + 1);
        bits |= (unsigned)(v.z != 0) << (i * 4 + 2);
        bits |= (unsigned)(v.w != 0) << (i * 4 + 3);
    }
    g_maskbits[w] = bits;
}

// fp32 -> fp16 (8 elems/thread), with scale
__global__ void cvt_f16(const float4* __restrict__ src, uint4* __restrict__ dst,
                        float scale, int n16) {
    int i = blockIdx.x * blockDim.x + threadIdx.x;
    if (i >= n16) return;
    float4 a = src[2 * i], b = src[2 * i + 1];
    uint4 w;
    w.x = pack_h2(a.x * scale, a.y * scale);
    w.y = pack_h2(a.z * scale, a.w * scale);
    w.z = pack_h2(b.x * scale, b.y * scale);
    w.w = pack_h2(b.z * scale, b.w * scale);
    dst[i] = w;
}

// -------- main kernel: 4 warps/CTA, register-resident P, 4 CTAs/SM --------
__global__ __launch_bounds__(NTH, 4)
void fa_mma(float* __restrict__ go)
{
    extern __shared__ char smem[];
    const uint32_t sb = smem_u32(smem);
    const int tid = threadIdx.x;
    const int lane = tid & 31, wid = tid >> 5;
    const int bh = blockIdx.y;
    const int q0 = blockIdx.x * BQ;
    const int m0 = wid * 16;

    const size_t row_bytes = 128;
    const char* gqh = (const char*)g_qh + ((size_t)bh * TDIM + q0) * row_bytes;
    const char* gkh0 = (const char*)g_kh + (size_t)bh * TDIM * row_bytes;
    const char* gvh0 = (const char*)g_vh + (size_t)bh * TDIM * row_bytes;
    float* ob = go + (size_t)bh * TDIM * DDIM;

    // ---- K/V tile 0 into stage 0 (8 cp16/thread: KH, VH) ----
    #pragma unroll
    for (int j = 0; j < 4; ++j) {
        uint32_t byte = (tid + j * NTH) * 16;
        uint32_t sw = swz(byte);
        cp16(sb + sw,        gkh0 + byte);
        cp16(sb + 8192 + sw, gvh0 + byte);
    }
    CP_COMMIT();

    const int g  = lane >> 2;
    const int tq = lane & 3;
    const int r0loc = m0 + g;

    // ---- Q fragments straight from global (A-frag = 2 consecutive fp16) ----
    uint32_t aQ[4][4];
    #pragma unroll
    for (int ks = 0; ks < 4; ++ks) {
        uint32_t cb = ks * 32 + tq * 4;
        const char* r0h = gqh + (size_t)r0loc * 128;
        const char* r1h = gqh + (size_t)(r0loc + 8) * 128;
        aQ[ks][0] = *(const uint32_t*)(r0h + cb);
        aQ[ks][1] = *(const uint32_t*)(r1h + cb);
        aQ[ks][2] = *(const uint32_t*)(r0h + cb + 16);
        aQ[ks][3] = *(const uint32_t*)(r1h + cb + 16);
    }

    // fragment address pieces (B operands via ldmatrix)
    const uint32_t brow  = ((lane >> 4) & 1) * 8 + (lane & 7);
    const uint32_t bcol0 = ((lane >> 3) & 1) * 16;
    const uint32_t trow0 = ((lane >> 3) & 1) * 8 + (lane & 7);
    const uint32_t tcol0 = ((lane >> 4) & 1) * 16;

    float oreg[8][4];
    #pragma unroll
    for (int i = 0; i < 8; ++i)
        #pragma unroll
        for (int j = 0; j < 4; ++j) oreg[i][j] = 0.f;
    float lsum0 = 0.f, lsum1 = 0.f;

    CP_WAIT(0);
    __syncthreads();

    for (int kt = 0; kt < KTILES; ++kt) {
        // ---- prefetch next tile into alternate stage ----
        if (kt + 1 < KTILES) {
            const size_t toff = (size_t)(kt + 1) * BK * row_bytes;
            uint32_t base = sb + ((kt + 1) & 1) * KV_STAGE;
            #pragma unroll
            for (int j = 0; j < 4; ++j) {
                uint32_t byte = (tid + j * NTH) * 16;
                uint32_t sw = swz(byte);
                cp16(base + sw,        gkh0 + toff + byte);
                cp16(base + 8192 + sw, gvh0 + toff + byte);
            }
            CP_COMMIT();
        }

        // early mask fetch
        unsigned long long mw0 =
            *(const unsigned long long*)(g_maskbits + (size_t)(q0 + r0loc) * (TDIM / 32) + kt * 2);
        unsigned long long mw1 =
            *(const unsigned long long*)(g_maskbits + (size_t)(q0 + r0loc + 8) * (TDIM / 32) + kt * 2);

        const uint32_t kvb = sb + (kt & 1) * KV_STAGE;
        const uint32_t khb = kvb, vhb = kvb + 8192;

        // ---- S = Q K^T (single-term fp16) ----
        float s[8][4];
        #pragma unroll
        for (int i = 0; i < 8; ++i)
            #pragma unroll
            for (int j = 0; j < 4; ++j) s[i][j] = 0.f;

        #pragma unroll
        for (int ks = 0; ks < 4; ++ks) {
            #pragma unroll
            for (int np = 0; np < 4; ++np) {
                uint32_t sw = swz((np * 16 + brow) * 128 + ks * 32 + bcol0);
                uint32_t bHf[4];
                ldsm_x4(bHf, khb + sw);
                mma16816(s[2 * np],     aQ[ks], bHf[0], bHf[1]);
                mma16816(s[2 * np + 1], aQ[ks], bHf[2], bHf[3]);
            }
        }

        // ---- mask + exp2 -> register-resident P (A-frag layout, no smem) ----
        uint32_t aP[4][4];
        #pragma unroll
        for (int ks = 0; ks < 4; ++ks) {
            #pragma unroll
            for (int h = 0; h < 2; ++h) {          // n8-tile 2ks+h
                int ng = 2 * ks + h;
                int c = ng * 8 + tq * 2;
                float p0 = ((mw0 >> c) & 1ULL)       ? 0.f : ex2f(s[ng][0]);
                float p1 = ((mw0 >> (c + 1)) & 1ULL) ? 0.f : ex2f(s[ng][1]);
                float p2 = ((mw1 >> c) & 1ULL)       ? 0.f : ex2f(s[ng][2]);
                float p3 = ((mw1 >> (c + 1)) & 1ULL) ? 0.f : ex2f(s[ng][3]);
                lsum0 += p0 + p1;
                lsum1 += p2 + p3;
                aP[ks][2 * h]     = pack_h2(p0, p1);   // row g
                aP[ks][2 * h + 1] = pack_h2(p2, p3);   // row g+8
            }
        }

        // ---- O += P V (single-term fp16), V via ldmatrix.trans ----
        #pragma unroll
        for (int ks = 0; ks < 4; ++ks) {
            #pragma unroll
            for (int np = 0; np < 4; ++np) {
                uint32_t swB = swz((ks * 16 + trow0) * 128 + np * 32 + tcol0);
                uint32_t bVf[4];
                ldsm_x4_t(bVf, vhb + swB);
                mma16816(oreg[2 * np],     aP[ks], bVf[0], bVf[1]);
                mma16816(oreg[2 * np + 1], aP[ks], bVf[2], bVf[3]);
            }
        }

        // next tile resident + everyone done with this stage
        if (kt + 1 < KTILES) CP_WAIT(0);
        __syncthreads();
    }

    // ---- epilogue ----
    #pragma unroll
    for (int off = 1; off <= 2; off <<= 1) {
        lsum0 += __shfl_xor_sync(0xffffffffu, lsum0, off);
        lsum1 += __shfl_xor_sync(0xffffffffu, lsum1, off);
    }
    float inv0 = 1.f / lsum0;
    float inv1 = 1.f / lsum1;

    float* orow0 = ob + (size_t)(q0 + r0loc) * DDIM;
    float* orow1 = ob + (size_t)(q0 + r0loc + 8) * DDIM;
    #pragma unroll
    for (int ng = 0; ng < 8; ++ng) {
        int c = ng * 8 + tq * 2;
        *(float2*)(orow0 + c) = make_float2(oreg[ng][0] * inv0, oreg[ng][1] * inv0);
        *(float2*)(orow1 + c) = make_float2(oreg[ng][2] * inv1, oreg[ng][3] * inv1);
    }
}

extern "C" void kernel_launch(void* const* d_in, const int* in_sizes, int n_in,
                              void* d_out, int out_size) {
    const float* q = (const float*)d_in[0];
    const float* k = (const float*)d_in[1];
    const float* v = (const float*)d_in[2];
    const int* mask = (const int*)d_in[3];
    float* out = (float*)d_out;

    uint4 *qh, *kh, *vh;
    cudaGetSymbolAddress((void**)&qh, g_qh);
    cudaGetSymbolAddress((void**)&kh, g_kh);
    cudaGetSymbolAddress((void**)&vh, g_vh);

    pack_mask<<<(TDIM * TDIM / 32 + 255) / 256, 256>>>(mask);

    const int n16 = (int)(NELEM / 8);
    // Q scale folds softmax 1/sqrt(D) and log2(e): exp(s) == exp2(s*log2e)
    const float qscale = 0.125f * 1.44269504088896340736f;
    cvt_f16<<<(n16 + 255) / 256, 256>>>((const float4*)q, qh, qscale, n16);
    cvt_f16<<<(n16 + 255) / 256, 256>>>((const float4*)k, kh, 1.0f, n16);
    cvt_f16<<<(n16 + 255) / 256, 256>>>((const float4*)v, vh, 1.0f, n16);

    cudaFuncSetAttribute(fa_mma, cudaFuncAttributeMaxDynamicSharedMemorySize, SMEM_BYTES);
    dim3 grid(TDIM / BQ, BH);
    fa_mma<<<grid, NTH, SMEM_BYTES>>>(out);
}